// round 2
// baseline (speedup 1.0000x reference)
#include <cuda_runtime.h>

#define V     2048
#define DIN   64
#define DOUT  64
#define NB    64   // A*B = 8*8

// Scratch (no cudaMalloc allowed)
__device__ float g_xtmp[(size_t)NB * V * DOUT];  // 33.5 MB projected features
__device__ float g_colsum[V];
__device__ float g_rinv[V];

// ---------------------------------------------------------------------------
// Kernel 1a: zero the column-sum accumulator (must be re-zeroed each replay)
// ---------------------------------------------------------------------------
__global__ void zero_colsum_kernel() {
    int i = blockIdx.x * blockDim.x + threadIdx.x;
    if (i < V) g_colsum[i] = 0.0f;
}

// ---------------------------------------------------------------------------
// Kernel 1b: partial column sums of adj (sum over rows i for each column j)
// grid (8, 32): block (bx,by) covers columns bx*256.., rows by*64..
// Coalesced: thread t owns column j = bx*256+t, strides down 64 rows.
// ---------------------------------------------------------------------------
__global__ void __launch_bounds__(256) colsum_partial_kernel(const float* __restrict__ adj) {
    int j  = blockIdx.x * 256 + threadIdx.x;
    int i0 = blockIdx.y * 64;
    float s = 0.0f;
#pragma unroll 8
    for (int i = 0; i < 64; i++) {
        s += adj[(size_t)(i0 + i) * V + j];
    }
    atomicAdd(&g_colsum[j], s);
}

// ---------------------------------------------------------------------------
// Kernel 1c: r_inv = rsqrt(colsum)
// ---------------------------------------------------------------------------
__global__ void finalize_rinv_kernel() {
    int i = blockIdx.x * blockDim.x + threadIdx.x;
    if (i < V) g_rinv[i] = rsqrtf(g_colsum[i]);
}

// ---------------------------------------------------------------------------
// Kernel 2: projection  x_tmp[row, e] = sum_k x[row, k] * W[k, e]
// rows = NB*V = 131072. Each block handles 64 rows x all 64 output cols.
// ---------------------------------------------------------------------------
__global__ void __launch_bounds__(256) project_kernel(const float* __restrict__ x,
                                                      const float* __restrict__ w) {
    __shared__ __align__(16) float Ws[DIN][DOUT];      // 16 KB, stride 64 keeps float4 alignment
    __shared__ float Xs[64][DIN + 1];                  // padded rows, scalar access

    int tid  = threadIdx.x;
    int row0 = blockIdx.x * 64;

    // Load W (4096 floats)
#pragma unroll
    for (int idx = tid; idx < DIN * DOUT; idx += 256) {
        Ws[idx / DOUT][idx % DOUT] = w[idx];
    }
    // Load 64 rows of x (4096 floats), coalesced
#pragma unroll
    for (int idx = tid; idx < 64 * DIN; idx += 256) {
        Xs[idx / DIN][idx % DIN] = x[(size_t)(row0 + idx / DIN) * DIN + (idx % DIN)];
    }
    __syncthreads();

    // 4 threads per row, 16 output columns each
    int row = tid >> 2;
    int e0  = (tid & 3) * 16;

    float acc[16];
#pragma unroll
    for (int e = 0; e < 16; e++) acc[e] = 0.0f;

#pragma unroll 4
    for (int k = 0; k < DIN; k++) {
        float xv = Xs[row][k];
        const float4* wr = (const float4*)&Ws[k][e0];
        float4 w0 = wr[0], w1 = wr[1], w2 = wr[2], w3 = wr[3];
        acc[0]  += xv * w0.x;  acc[1]  += xv * w0.y;  acc[2]  += xv * w0.z;  acc[3]  += xv * w0.w;
        acc[4]  += xv * w1.x;  acc[5]  += xv * w1.y;  acc[6]  += xv * w1.z;  acc[7]  += xv * w1.w;
        acc[8]  += xv * w2.x;  acc[9]  += xv * w2.y;  acc[10] += xv * w2.z;  acc[11] += xv * w2.w;
        acc[12] += xv * w3.x;  acc[13] += xv * w3.y;  acc[14] += xv * w3.z;  acc[15] += xv * w3.w;
    }

    float* dst = &g_xtmp[(size_t)(row0 + row) * DOUT + e0];
#pragma unroll
    for (int q = 0; q < 4; q++) {
        float4 o = make_float4(acc[q * 4 + 0], acc[q * 4 + 1], acc[q * 4 + 2], acc[q * 4 + 3]);
        *(float4*)(dst + q * 4) = o;
    }
}

// ---------------------------------------------------------------------------
// Kernel 3: aggregation GEMM + bias + relu
//   out[ab, j, d] = relu(bias[d] + rinv[j] * sum_v (adj[v,j]*rinv[v]) * xtmp[ab,v,d])
// Tile: 128 (j) x 64 (d) per CTA, K = 2048 in chunks of 16.
// 256 threads, each computes an 8x4 microtile.
// grid: (16 j-tiles, 64 ab)
// ---------------------------------------------------------------------------
__global__ void __launch_bounds__(256) agg_kernel(const float* __restrict__ adj,
                                                  const float* __restrict__ bias,
                                                  float* __restrict__ out) {
    __shared__ __align__(16) float As[16][132];  // row stride 528B = 33*16, float4-safe
    __shared__ __align__(16) float Bs[16][68];   // row stride 272B = 17*16, float4-safe

    int ab  = blockIdx.y;
    int j0  = blockIdx.x * 128;
    int tid = threadIdx.x;
    int ty  = tid >> 4;          // 0..15
    int tx  = tid & 15;          // 0..15
    int jb  = ty * 8;            // j offset within tile
    int db  = tx * 4;            // d offset within tile

    const float* xt = g_xtmp + (size_t)ab * V * DOUT;

    float acc[8][4];
#pragma unroll
    for (int jj = 0; jj < 8; jj++)
#pragma unroll
        for (int dd = 0; dd < 4; dd++) acc[jj][dd] = 0.0f;

    for (int k0 = 0; k0 < V; k0 += 16) {
        // Load A tile: adj[k0+kk][j0 + 0..127] * rinv[k0+kk]
        // 16*128 = 2048 floats = 512 float4; 2 per thread
#pragma unroll
        for (int q = 0; q < 2; q++) {
            int idx = tid + q * 256;        // 0..511
            int kk  = idx >> 5;             // /32
            int j4  = idx & 31;
            float4 a = *(const float4*)&adj[(size_t)(k0 + kk) * V + j0 + j4 * 4];
            float rv = g_rinv[k0 + kk];
            float4 as = make_float4(a.x * rv, a.y * rv, a.z * rv, a.w * rv);
            *(float4*)&As[kk][j4 * 4] = as;
        }
        // Load B tile: xtmp[ab][k0+kk][0..63]; 16*64 = 1024 floats = 256 float4
        {
            int kk = tid >> 4;
            int d4 = tid & 15;
            float4 b = *(const float4*)&xt[(size_t)(k0 + kk) * DOUT + d4 * 4];
            *(float4*)&Bs[kk][d4 * 4] = b;
        }
        __syncthreads();

#pragma unroll
        for (int kk = 0; kk < 16; kk++) {
            float4 b  = *(const float4*)&Bs[kk][db];
            float4 a0 = *(const float4*)&As[kk][jb];
            float4 a1 = *(const float4*)&As[kk][jb + 4];
            float av[8] = {a0.x, a0.y, a0.z, a0.w, a1.x, a1.y, a1.z, a1.w};
#pragma unroll
            for (int jj = 0; jj < 8; jj++) {
                acc[jj][0] += av[jj] * b.x;
                acc[jj][1] += av[jj] * b.y;
                acc[jj][2] += av[jj] * b.z;
                acc[jj][3] += av[jj] * b.w;
            }
        }
        __syncthreads();
    }

    // Epilogue: scale by rinv[j], add bias, relu, store float4
    float4 bi = *(const float4*)&bias[db];
#pragma unroll
    for (int jj = 0; jj < 8; jj++) {
        int j    = j0 + jb + jj;
        float rj = g_rinv[j];
        float4 o;
        o.x = fmaxf(bi.x + rj * acc[jj][0], 0.0f);
        o.y = fmaxf(bi.y + rj * acc[jj][1], 0.0f);
        o.z = fmaxf(bi.z + rj * acc[jj][2], 0.0f);
        o.w = fmaxf(bi.w + rj * acc[jj][3], 0.0f);
        *(float4*)&out[((size_t)ab * V + j) * DOUT + db] = o;
    }
}

// ---------------------------------------------------------------------------
extern "C" void kernel_launch(void* const* d_in, const int* in_sizes, int n_in,
                              void* d_out, int out_size) {
    const float* adj  = (const float*)d_in[0];
    const float* x    = (const float*)d_in[1];
    const float* w    = (const float*)d_in[2];
    const float* bias = (const float*)d_in[3];
    float* out        = (float*)d_out;

    zero_colsum_kernel<<<8, 256>>>();
    colsum_partial_kernel<<<dim3(8, 32), 256>>>(adj);
    finalize_rinv_kernel<<<8, 256>>>();
    project_kernel<<<(NB * V) / 64, 256>>>(x, w);
    agg_kernel<<<dim3(V / 128, NB), 256>>>(adj, bias, out);
}

// round 5
// speedup vs baseline: 2.8589x; 2.8589x over previous
#include <cuda_runtime.h>
#include <cstdint>

#define V     2048
#define DIN   64
#define DOUT  64
#define NB    64            // A*B = 8*8
#define NCOL  (NB * DOUT)   // 4096 columns of the big GEMM

// ---------------- scratch (device globals; no cudaMalloc allowed) ----------
__device__ float g_adjT[(size_t)V * V];      // 16 MB: adjT[j][v] = adj[v][j]*rinv[v], tf32-rounded
__device__ float g_xT[(size_t)NCOL * V];     // 32 MB: xT[c][v] = (x@W)[ab,v,d], c=ab*64+d, tf32-rounded
__device__ float g_colsum[V];
__device__ float g_rinv[V];

// ---------------- helpers ---------------------------------------------------
__device__ __forceinline__ uint32_t smem_u32(const void* p) {
    uint32_t a;
    asm("{ .reg .u64 t; cvta.to.shared.u64 t, %1; cvt.u32.u64 %0, t; }" : "=r"(a) : "l"(p));
    return a;
}
__device__ __forceinline__ float to_tf32(float x) {
    uint32_t r;
    asm("cvt.rna.tf32.f32 %0, %1;" : "=r"(r) : "f"(x));
    return __uint_as_float(r);
}
#define CP_ASYNC16(dst, src) \
    asm volatile("cp.async.cg.shared.global [%0], [%1], 16;" :: "r"(dst), "l"(src) : "memory")
#define CP_COMMIT() asm volatile("cp.async.commit_group;" ::: "memory")
#define CP_WAIT(n)  asm volatile("cp.async.wait_group %0;" :: "n"(n) : "memory")

// m16n8k8 tf32 mma: D += A*B, A row-major 16x8, B col-major 8x8, fp32 accum
__device__ __forceinline__ void mma_tf32(float* d, const uint32_t* a, const uint32_t* b) {
    asm volatile(
        "mma.sync.aligned.m16n8k8.row.col.f32.tf32.tf32.f32 "
        "{%0,%1,%2,%3}, {%4,%5,%6,%7}, {%8,%9}, {%0,%1,%2,%3};"
        : "+f"(d[0]), "+f"(d[1]), "+f"(d[2]), "+f"(d[3])
        : "r"(a[0]), "r"(a[1]), "r"(a[2]), "r"(a[3]), "r"(b[0]), "r"(b[1]));
}

// ---------------------------------------------------------------------------
// colsum / rinv  (reference: r_inv[j] = (sum_i adj[i][j])^-0.5)
// ---------------------------------------------------------------------------
__global__ void zero_colsum_kernel() {
    int i = blockIdx.x * blockDim.x + threadIdx.x;
    if (i < V) g_colsum[i] = 0.0f;
}
__global__ void __launch_bounds__(256) colsum_partial_kernel(const float* __restrict__ adj) {
    int j  = blockIdx.x * 256 + threadIdx.x;
    int i0 = blockIdx.y * 64;
    float s = 0.0f;
#pragma unroll 8
    for (int i = 0; i < 64; i++) s += adj[(size_t)(i0 + i) * V + j];
    atomicAdd(&g_colsum[j], s);
}
__global__ void finalize_rinv_kernel() {
    int i = blockIdx.x * blockDim.x + threadIdx.x;
    if (i < V) g_rinv[i] = rsqrtf(g_colsum[i]);
}

// ---------------------------------------------------------------------------
// transpose: adjT[j][v] = tf32(adj[v][j] * rinv[v])
// ---------------------------------------------------------------------------
__global__ void __launch_bounds__(256) transpose_kernel(const float* __restrict__ adj) {
    __shared__ float t[32][33];
    int tx = threadIdx.x & 31, ty = threadIdx.x >> 5;   // 32 x 8
    int j0 = blockIdx.x * 32, v0 = blockIdx.y * 32;
#pragma unroll
    for (int i = 0; i < 4; i++) {
        int vy = ty + i * 8;
        t[vy][tx] = adj[(size_t)(v0 + vy) * V + j0 + tx];
    }
    __syncthreads();
    float rv = g_rinv[v0 + tx];
#pragma unroll
    for (int i = 0; i < 4; i++) {
        int jy = ty + i * 8;
        g_adjT[(size_t)(j0 + jy) * V + v0 + tx] = to_tf32(t[tx][jy] * rv);
    }
}

// ---------------------------------------------------------------------------
// project: xT[(ab*64+d)][v] = tf32( sum_k x[ab,v,k] * W[k,d] )
// block: 64 v-rows x 64 d for one ab. thread: 4 rows x 4 cols.
// ---------------------------------------------------------------------------
__global__ void __launch_bounds__(256) project_kernel(const float* __restrict__ x,
                                                      const float* __restrict__ w) {
    __shared__ __align__(16) float Ws[DIN][DOUT];
    __shared__ __align__(16) float XsT[DIN][68];       // [k][v-row], stride 272B
    int tid = threadIdx.x;
    int ab  = blockIdx.y;
    int v0  = blockIdx.x * 64;

    {
        const float4* src = (const float4*)w;
        float4* dst = (float4*)Ws;
#pragma unroll
        for (int s = tid; s < 1024; s += 256) dst[s] = src[s];
    }
    {
        const float* xb = x + ((size_t)ab * V + v0) * DIN;
#pragma unroll
        for (int s = tid; s < 1024; s += 256) {
            int r = s >> 4, kq = s & 15;
            float4 f = *(const float4*)&xb[(size_t)r * DIN + kq * 4];
            XsT[kq * 4 + 0][r] = f.x;
            XsT[kq * 4 + 1][r] = f.y;
            XsT[kq * 4 + 2][r] = f.z;
            XsT[kq * 4 + 3][r] = f.w;
        }
    }
    __syncthreads();

    int dg = tid & 15;      // cols dg*4..+3
    int rg = tid >> 4;      // rows rg*4..+3

    float acc[4][4];
#pragma unroll
    for (int a = 0; a < 4; a++)
#pragma unroll
        for (int b = 0; b < 4; b++) acc[a][b] = 0.0f;

#pragma unroll
    for (int k = 0; k < DIN; k++) {
        float4 xv = *(const float4*)&XsT[k][rg * 4];
        float4 wv = *(const float4*)&Ws[k][dg * 4];
        acc[0][0] += xv.x * wv.x; acc[0][1] += xv.x * wv.y; acc[0][2] += xv.x * wv.z; acc[0][3] += xv.x * wv.w;
        acc[1][0] += xv.y * wv.x; acc[1][1] += xv.y * wv.y; acc[1][2] += xv.y * wv.z; acc[1][3] += xv.y * wv.w;
        acc[2][0] += xv.z * wv.x; acc[2][1] += xv.z * wv.y; acc[2][2] += xv.z * wv.z; acc[2][3] += xv.z * wv.w;
        acc[3][0] += xv.w * wv.x; acc[3][1] += xv.w * wv.y; acc[3][2] += xv.w * wv.z; acc[3][3] += xv.w * wv.w;
    }

#pragma unroll
    for (int dd = 0; dd < 4; dd++) {
        int c = ab * 64 + dg * 4 + dd;
        float4 o;
        o.x = to_tf32(acc[0][dd]);
        o.y = to_tf32(acc[1][dd]);
        o.z = to_tf32(acc[2][dd]);
        o.w = to_tf32(acc[3][dd]);
        *(float4*)&g_xT[(size_t)c * V + v0 + rg * 4] = o;
    }
}

// ---------------------------------------------------------------------------
// agg: mma.sync tf32 GEMM  D[j, c] = sum_v adjT[j,v] * xT[c,v]
//   CTA tile 128(j) x 256(c), 8 warps, warp tile 64x64 (4 m-frags x 8 n-frags)
//   K chunks of 32, cp.async double-buffered; smem row stride 36 floats
//   (144B: 16B-aligned for cp.async AND conflict-free fragment LDS)
//   epilogue: out[ab,j,d] = relu(bias[d] + rinv[j]*D[j, ab*64+d])
// ---------------------------------------------------------------------------
#define MT 128
#define NT 256
#define KC 32
#define NCHUNK (V / KC)           // 64
#define LDS_STRIDE 36             // floats per smem row
#define A_FLOATS (MT * LDS_STRIDE)    // 4608
#define B_FLOATS (NT * LDS_STRIDE)    // 9216
#define SM_FLOATS (2 * A_FLOATS + 2 * B_FLOATS)   // 27648 floats = 110592 B
#define SM_BYTES  (SM_FLOATS * 4)

__device__ __forceinline__ void load_chunk(uint32_t smem_base, float* smem, int buf,
                                           int j0, int n0, int k0, int tid) {
    uint32_t sa = smem_base + (uint32_t)(buf * A_FLOATS) * 4u;
    uint32_t sb = smem_base + (uint32_t)(2 * A_FLOATS + buf * B_FLOATS) * 4u;
    // A: 128 rows x 32 floats = 1024 16B-segments (4/thread)
#pragma unroll
    for (int q = 0; q < 4; q++) {
        int s = tid + q * 256;
        int r = s >> 3, o = s & 7;
        uint32_t dst = sa + (uint32_t)(r * LDS_STRIDE + o * 4) * 4u;
        const float* src = &g_adjT[(size_t)(j0 + r) * V + k0 + o * 4];
        CP_ASYNC16(dst, src);
    }
    // B: 256 rows x 32 floats = 2048 16B-segments (8/thread)
#pragma unroll
    for (int q = 0; q < 8; q++) {
        int s = tid + q * 256;
        int r = s >> 3, o = s & 7;
        uint32_t dst = sb + (uint32_t)(r * LDS_STRIDE + o * 4) * 4u;
        const float* src = &g_xT[(size_t)(n0 + r) * V + k0 + o * 4];
        CP_ASYNC16(dst, src);
    }
}

__global__ void __launch_bounds__(256, 1) agg_mma_kernel(const float* __restrict__ bias,
                                                         float* __restrict__ out) {
    extern __shared__ __align__(16) float smem[];
    uint32_t smem_base = smem_u32(smem);
    int tid  = threadIdx.x;
    int wid  = tid >> 5, lane = tid & 31;
    int j0   = blockIdx.x * MT;
    int n0   = blockIdx.y * NT;
    int m0w  = (wid & 1) * 64;       // warp's m offset within CTA tile
    int n0w  = (wid >> 1) * 64;      // warp's n offset within CTA tile
    int lg   = lane >> 2;            // 0..7
    int lc   = lane & 3;             // 0..3

    float d[4][8][4];
#pragma unroll
    for (int i = 0; i < 4; i++)
#pragma unroll
        for (int j = 0; j < 8; j++)
#pragma unroll
            for (int q = 0; q < 4; q++) d[i][j][q] = 0.0f;

    // prologue: preload chunks 0 and 1
    load_chunk(smem_base, smem, 0, j0, n0, 0, tid);   CP_COMMIT();
    load_chunk(smem_base, smem, 1, j0, n0, KC, tid);  CP_COMMIT();

    for (int i = 0; i < NCHUNK; i++) {
        if (i < NCHUNK - 1) { CP_WAIT(1); } else { CP_WAIT(0); }
        __syncthreads();

        int buf = i & 1;
        const float* As = smem + buf * A_FLOATS;
        const float* Bs = smem + 2 * A_FLOATS + buf * B_FLOATS;

#pragma unroll
        for (int k8 = 0; k8 < 4; k8++) {
            int kb = k8 * 8;
            uint32_t a[4][4], b[8][2];
#pragma unroll
            for (int fi = 0; fi < 4; fi++) {
                const float* ap = As + (m0w + fi * 16 + lg) * LDS_STRIDE + kb + lc;
                a[fi][0] = __float_as_uint(ap[0]);
                a[fi][1] = __float_as_uint(ap[8 * LDS_STRIDE]);
                a[fi][2] = __float_as_uint(ap[4]);
                a[fi][3] = __float_as_uint(ap[8 * LDS_STRIDE + 4]);
            }
#pragma unroll
            for (int fj = 0; fj < 8; fj++) {
                const float* bp = Bs + (n0w + fj * 8 + lg) * LDS_STRIDE + kb + lc;
                b[fj][0] = __float_as_uint(bp[0]);
                b[fj][1] = __float_as_uint(bp[4]);
            }
#pragma unroll
            for (int fi = 0; fi < 4; fi++)
#pragma unroll
                for (int fj = 0; fj < 8; fj++)
                    mma_tf32(d[fi][fj], a[fi], b[fj]);
        }
        __syncthreads();

        if (i + 2 < NCHUNK) {
            load_chunk(smem_base, smem, buf, j0, n0, (i + 2) * KC, tid);
            CP_COMMIT();
        }
    }

    // epilogue: D frag mapping — c0,c1 at row lg col 2*lc(,+1); c2,c3 at row lg+8
#pragma unroll
    for (int fi = 0; fi < 4; fi++) {
        int row_lo = j0 + m0w + fi * 16 + lg;
        int row_hi = row_lo + 8;
        float rlo = g_rinv[row_lo];
        float rhi = g_rinv[row_hi];
#pragma unroll
        for (int fj = 0; fj < 8; fj++) {
            int c  = n0 + n0w + fj * 8 + lc * 2;
            int ab = c >> 6;
            int dd = c & 63;
            float2 bi = *(const float2*)&bias[dd];
            float2 olo, ohi;
            olo.x = fmaxf(bi.x + rlo * d[fi][fj][0], 0.0f);
            olo.y = fmaxf(bi.y + rlo * d[fi][fj][1], 0.0f);
            ohi.x = fmaxf(bi.x + rhi * d[fi][fj][2], 0.0f);
            ohi.y = fmaxf(bi.y + rhi * d[fi][fj][3], 0.0f);
            *(float2*)&out[((size_t)ab * V + row_lo) * DOUT + dd] = olo;
            *(float2*)&out[((size_t)ab * V + row_hi) * DOUT + dd] = ohi;
        }
    }
}

// ---------------------------------------------------------------------------
extern "C" void kernel_launch(void* const* d_in, const int* in_sizes, int n_in,
                              void* d_out, int out_size) {
    const float* adj  = (const float*)d_in[0];
    const float* x    = (const float*)d_in[1];
    const float* w    = (const float*)d_in[2];
    const float* bias = (const float*)d_in[3];
    float* out        = (float*)d_out;

    cudaFuncSetAttribute(agg_mma_kernel, cudaFuncAttributeMaxDynamicSharedMemorySize, SM_BYTES);

    zero_colsum_kernel<<<8, 256>>>();
    colsum_partial_kernel<<<dim3(8, 32), 256>>>(adj);
    finalize_rinv_kernel<<<8, 256>>>();
    transpose_kernel<<<dim3(64, 64), 256>>>(adj);
    project_kernel<<<dim3(V / 64, NB), 256>>>(x, w);
    agg_mma_kernel<<<dim3(V / MT, NCOL / NT), 256, SM_BYTES>>>(bias, out);
}

// round 6
// speedup vs baseline: 4.6597x; 1.6299x over previous
#include <cuda_runtime.h>
#include <cuda_bf16.h>
#include <cstdint>

#define V     2048
#define DIN   64
#define DOUT  64
#define NB    64            // A*B = 8*8
#define NCOL  (NB * DOUT)   // 4096 columns of the big GEMM

// ---------------- scratch (device globals; no cudaMalloc allowed) ----------
__device__ __nv_bfloat16 g_adjT[(size_t)V * V];   // 8 MB: adjT[j][v] = bf16(adj[v][j]*rinv[v])
__device__ __nv_bfloat16 g_xT[(size_t)NCOL * V];  // 16 MB: xT[c][v] = bf16((x@W)[ab,v,d]), c=ab*64+d
__device__ float g_colsum[V];
__device__ float g_rinv[V];

// ---------------- helpers ---------------------------------------------------
__device__ __forceinline__ uint32_t smem_u32(const void* p) {
    uint32_t a;
    asm("{ .reg .u64 t; cvta.to.shared.u64 t, %1; cvt.u32.u64 %0, t; }" : "=r"(a) : "l"(p));
    return a;
}
#define CP_ASYNC16(dst, src) \
    asm volatile("cp.async.cg.shared.global [%0], [%1], 16;" :: "r"(dst), "l"(src) : "memory")
#define CP_COMMIT() asm volatile("cp.async.commit_group;" ::: "memory")
#define CP_WAIT(n)  asm volatile("cp.async.wait_group %0;" :: "n"(n) : "memory")

// m16n8k16 bf16 mma: D += A*B, A row-major 16x16, B col-major 16x8, fp32 accum
__device__ __forceinline__ void mma_bf16(float* d, const uint32_t* a, const uint32_t* b) {
    asm volatile(
        "mma.sync.aligned.m16n8k16.row.col.f32.bf16.bf16.f32 "
        "{%0,%1,%2,%3}, {%4,%5,%6,%7}, {%8,%9}, {%0,%1,%2,%3};"
        : "+f"(d[0]), "+f"(d[1]), "+f"(d[2]), "+f"(d[3])
        : "r"(a[0]), "r"(a[1]), "r"(a[2]), "r"(a[3]), "r"(b[0]), "r"(b[1]));
}

// ---------------------------------------------------------------------------
// colsum / rinv  (reference: r_inv[j] = (sum_i adj[i][j])^-0.5)
// ---------------------------------------------------------------------------
__global__ void zero_colsum_kernel() {
    int i = blockIdx.x * blockDim.x + threadIdx.x;
    if (i < V) g_colsum[i] = 0.0f;
}
__global__ void __launch_bounds__(256) colsum_partial_kernel(const float* __restrict__ adj) {
    int j  = blockIdx.x * 256 + threadIdx.x;
    int i0 = blockIdx.y * 64;
    float s = 0.0f;
#pragma unroll 8
    for (int i = 0; i < 64; i++) s += adj[(size_t)(i0 + i) * V + j];
    atomicAdd(&g_colsum[j], s);
}
__global__ void finalize_rinv_kernel() {
    int i = blockIdx.x * blockDim.x + threadIdx.x;
    if (i < V) g_rinv[i] = rsqrtf(g_colsum[i]);
}

// ---------------------------------------------------------------------------
// transpose: adjT[j][v] = bf16(adj[v][j] * rinv[v])
// ---------------------------------------------------------------------------
__global__ void __launch_bounds__(256) transpose_kernel(const float* __restrict__ adj) {
    __shared__ float t[32][33];
    int tx = threadIdx.x & 31, ty = threadIdx.x >> 5;   // 32 x 8
    int j0 = blockIdx.x * 32, v0 = blockIdx.y * 32;
#pragma unroll
    for (int i = 0; i < 4; i++) {
        int vy = ty + i * 8;
        t[vy][tx] = adj[(size_t)(v0 + vy) * V + j0 + tx];
    }
    __syncthreads();
    float rv = g_rinv[v0 + tx];
#pragma unroll
    for (int i = 0; i < 4; i++) {
        int jy = ty + i * 8;
        g_adjT[(size_t)(j0 + jy) * V + v0 + tx] = __float2bfloat16_rn(t[tx][jy] * rv);
    }
}

// ---------------------------------------------------------------------------
// project: xT[(ab*64+d)][v] = bf16( sum_k x[ab,v,k] * W[k,d] )
// block: 64 v-rows x 64 d for one ab. thread: 4 rows x 4 cols.
// ---------------------------------------------------------------------------
__global__ void __launch_bounds__(256) project_kernel(const float* __restrict__ x,
                                                      const float* __restrict__ w) {
    __shared__ __align__(16) float Ws[DIN][DOUT];
    __shared__ __align__(16) float XsT[DIN][68];       // [k][v-row], stride 272B
    int tid = threadIdx.x;
    int ab  = blockIdx.y;
    int v0  = blockIdx.x * 64;

    {
        const float4* src = (const float4*)w;
        float4* dst = (float4*)Ws;
#pragma unroll
        for (int s = tid; s < 1024; s += 256) dst[s] = src[s];
    }
    {
        const float* xb = x + ((size_t)ab * V + v0) * DIN;
#pragma unroll
        for (int s = tid; s < 1024; s += 256) {
            int r = s >> 4, kq = s & 15;
            float4 f = *(const float4*)&xb[(size_t)r * DIN + kq * 4];
            XsT[kq * 4 + 0][r] = f.x;
            XsT[kq * 4 + 1][r] = f.y;
            XsT[kq * 4 + 2][r] = f.z;
            XsT[kq * 4 + 3][r] = f.w;
        }
    }
    __syncthreads();

    int dg = tid & 15;      // cols dg*4..+3
    int rg = tid >> 4;      // rows rg*4..+3

    float acc[4][4];
#pragma unroll
    for (int a = 0; a < 4; a++)
#pragma unroll
        for (int b = 0; b < 4; b++) acc[a][b] = 0.0f;

#pragma unroll
    for (int k = 0; k < DIN; k++) {
        float4 xv = *(const float4*)&XsT[k][rg * 4];
        float4 wv = *(const float4*)&Ws[k][dg * 4];
        acc[0][0] += xv.x * wv.x; acc[0][1] += xv.x * wv.y; acc[0][2] += xv.x * wv.z; acc[0][3] += xv.x * wv.w;
        acc[1][0] += xv.y * wv.x; acc[1][1] += xv.y * wv.y; acc[1][2] += xv.y * wv.z; acc[1][3] += xv.y * wv.w;
        acc[2][0] += xv.z * wv.x; acc[2][1] += xv.z * wv.y; acc[2][2] += xv.z * wv.z; acc[2][3] += xv.z * wv.w;
        acc[3][0] += xv.w * wv.x; acc[3][1] += xv.w * wv.y; acc[3][2] += xv.w * wv.z; acc[3][3] += xv.w * wv.w;
    }

    // transposed write: for fixed d, 4 consecutive v -> 2x bf162 (8B)
#pragma unroll
    for (int dd = 0; dd < 4; dd++) {
        int c = ab * 64 + dg * 4 + dd;
        __nv_bfloat162 h0 = __floats2bfloat162_rn(acc[0][dd], acc[1][dd]);
        __nv_bfloat162 h1 = __floats2bfloat162_rn(acc[2][dd], acc[3][dd]);
        uint2 o = make_uint2(*(uint32_t*)&h0, *(uint32_t*)&h1);
        *(uint2*)&g_xT[(size_t)c * V + v0 + rg * 4] = o;
    }
}

// ---------------------------------------------------------------------------
// agg: mma.sync bf16 GEMM  D[j, c] = sum_v adjT[j,v] * xT[c,v]
//   CTA tile 128(j) x 256(c), 8 warps, warp tile 64x64 (4 m-frags x 8 n-frags)
//   K chunks of 64 (bf16 = 128B/row), cp.async double-buffered
//   smem row stride 72 halves (144B: 16B-aligned AND conflict-free LDS:
//   lane bank = (36*lg + lc) mod 32 = permutation of 0..31)
//   epilogue: out[ab,j,d] = relu(bias[d] + rinv[j]*D[j, ab*64+d])
// ---------------------------------------------------------------------------
#define MT 128
#define NT 256
#define KC 64
#define NCHUNK (V / KC)           // 32
#define LDS_STRIDE 72             // halves per smem row (144 B)
#define A_HALVES (MT * LDS_STRIDE)    // 9216
#define B_HALVES (NT * LDS_STRIDE)    // 18432
#define SM_BYTES ((2 * A_HALVES + 2 * B_HALVES) * 2)   // 110592 B

__device__ __forceinline__ void load_chunk(uint32_t smem_base, int buf,
                                           int j0, int n0, int k0, int tid) {
    uint32_t sa = smem_base + (uint32_t)(buf * A_HALVES) * 2u;
    uint32_t sb = smem_base + (uint32_t)(2 * A_HALVES + buf * B_HALVES) * 2u;
    // A: 128 rows x 128B = 1024 16B-segments (4/thread)
#pragma unroll
    for (int q = 0; q < 4; q++) {
        int s = tid + q * 256;
        int r = s >> 3, o = s & 7;
        uint32_t dst = sa + (uint32_t)(r * LDS_STRIDE + o * 8) * 2u;
        const __nv_bfloat16* src = &g_adjT[(size_t)(j0 + r) * V + k0 + o * 8];
        CP_ASYNC16(dst, src);
    }
    // B: 256 rows x 128B = 2048 16B-segments (8/thread)
#pragma unroll
    for (int q = 0; q < 8; q++) {
        int s = tid + q * 256;
        int r = s >> 3, o = s & 7;
        uint32_t dst = sb + (uint32_t)(r * LDS_STRIDE + o * 8) * 2u;
        const __nv_bfloat16* src = &g_xT[(size_t)(n0 + r) * V + k0 + o * 8];
        CP_ASYNC16(dst, src);
    }
}

__global__ void __launch_bounds__(256, 1) agg_mma_kernel(const float* __restrict__ bias,
                                                         float* __restrict__ out) {
    extern __shared__ __align__(16) __nv_bfloat16 smem[];
    uint32_t smem_base = smem_u32(smem);
    int tid  = threadIdx.x;
    int wid  = tid >> 5, lane = tid & 31;
    int j0   = blockIdx.x * MT;
    int n0   = blockIdx.y * NT;
    int m0w  = (wid & 1) * 64;       // warp's m offset within CTA tile
    int n0w  = (wid >> 1) * 64;      // warp's n offset within CTA tile
    int lg   = lane >> 2;            // 0..7
    int lc   = lane & 3;             // 0..3

    float d[4][8][4];
#pragma unroll
    for (int i = 0; i < 4; i++)
#pragma unroll
        for (int j = 0; j < 8; j++)
#pragma unroll
            for (int q = 0; q < 4; q++) d[i][j][q] = 0.0f;

    // prologue: preload chunks 0 and 1
    load_chunk(smem_base, 0, j0, n0, 0, tid);   CP_COMMIT();
    load_chunk(smem_base, 1, j0, n0, KC, tid);  CP_COMMIT();

    for (int i = 0; i < NCHUNK; i++) {
        if (i < NCHUNK - 1) { CP_WAIT(1); } else { CP_WAIT(0); }
        __syncthreads();

        int buf = i & 1;
        const __nv_bfloat16* As = smem + buf * A_HALVES;
        const __nv_bfloat16* Bs = smem + 2 * A_HALVES + buf * B_HALVES;

#pragma unroll
        for (int k16 = 0; k16 < 4; k16++) {
            int kb = k16 * 16;
            uint32_t a[4][4], b[8][2];
#pragma unroll
            for (int fi = 0; fi < 4; fi++) {
                const __nv_bfloat16* ap = As + (m0w + fi * 16 + lg) * LDS_STRIDE + kb + lc * 2;
                a[fi][0] = *(const uint32_t*)&ap[0];
                a[fi][1] = *(const uint32_t*)&ap[8 * LDS_STRIDE];
                a[fi][2] = *(const uint32_t*)&ap[8];
                a[fi][3] = *(const uint32_t*)&ap[8 * LDS_STRIDE + 8];
            }
#pragma unroll
            for (int fj = 0; fj < 8; fj++) {
                const __nv_bfloat16* bp = Bs + (n0w + fj * 8 + lg) * LDS_STRIDE + kb + lc * 2;
                b[fj][0] = *(const uint32_t*)&bp[0];
                b[fj][1] = *(const uint32_t*)&bp[8];
            }
#pragma unroll
            for (int fi = 0; fi < 4; fi++)
#pragma unroll
                for (int fj = 0; fj < 8; fj++)
                    mma_bf16(d[fi][fj], a[fi], b[fj]);
        }
        __syncthreads();

        if (i + 2 < NCHUNK) {
            load_chunk(smem_base, buf, j0, n0, (i + 2) * KC, tid);
            CP_COMMIT();
        }
    }

    // epilogue: D frag mapping — c0,c1 at row lg col 2*lc(,+1); c2,c3 at row lg+8
#pragma unroll
    for (int fi = 0; fi < 4; fi++) {
        int row_lo = j0 + m0w + fi * 16 + lg;
        int row_hi = row_lo + 8;
        float rlo = g_rinv[row_lo];
        float rhi = g_rinv[row_hi];
#pragma unroll
        for (int fj = 0; fj < 8; fj++) {
            int c  = n0 + n0w + fj * 8 + lc * 2;
            int ab = c >> 6;
            int dd = c & 63;
            float2 bi = *(const float2*)&bias[dd];
            float2 olo, ohi;
            olo.x = fmaxf(bi.x + rlo * d[fi][fj][0], 0.0f);
            olo.y = fmaxf(bi.y + rlo * d[fi][fj][1], 0.0f);
            ohi.x = fmaxf(bi.x + rhi * d[fi][fj][2], 0.0f);
            ohi.y = fmaxf(bi.y + rhi * d[fi][fj][3], 0.0f);
            *(float2*)&out[((size_t)ab * V + row_lo) * DOUT + dd] = olo;
            *(float2*)&out[((size_t)ab * V + row_hi) * DOUT + dd] = ohi;
        }
    }
}

// ---------------------------------------------------------------------------
extern "C" void kernel_launch(void* const* d_in, const int* in_sizes, int n_in,
                              void* d_out, int out_size) {
    const float* adj  = (const float*)d_in[0];
    const float* x    = (const float*)d_in[1];
    const float* w    = (const float*)d_in[2];
    const float* bias = (const float*)d_in[3];
    float* out        = (float*)d_out;

    cudaFuncSetAttribute(agg_mma_kernel, cudaFuncAttributeMaxDynamicSharedMemorySize, SM_BYTES);

    zero_colsum_kernel<<<8, 256>>>();
    colsum_partial_kernel<<<dim3(8, 32), 256>>>(adj);
    finalize_rinv_kernel<<<8, 256>>>();
    transpose_kernel<<<dim3(64, 64), 256>>>(adj);
    project_kernel<<<dim3(V / 64, NB), 256>>>(x, w);
    agg_mma_kernel<<<dim3(V / MT, NCOL / NT), 256, SM_BYTES>>>(bias, out);
}

// round 7
// speedup vs baseline: 5.6902x; 1.2212x over previous
#include <cuda_runtime.h>
#include <cuda_bf16.h>
#include <cstdint>

#define V     2048
#define DIN   64
#define DOUT  64
#define NB    64            // A*B = 8*8
#define NCOL  (NB * DOUT)   // 4096 columns of the big GEMM

// ---------------- scratch (device globals; no cudaMalloc allowed) ----------
__device__ __nv_bfloat16 g_adjT[(size_t)V * V];   // 8 MB: adjT[j][v] = bf16(adj[v][j]*rinv[v])
__device__ __nv_bfloat16 g_xT[(size_t)NCOL * V];  // 16 MB: xT[c][v] = bf16((x@W)[ab,v,d])
__device__ float g_colsum[V];
__device__ float g_rinv[V];

// ---------------- helpers ---------------------------------------------------
__device__ __forceinline__ uint32_t smem_u32(const void* p) {
    uint32_t a;
    asm("{ .reg .u64 t; cvta.to.shared.u64 t, %1; cvt.u32.u64 %0, t; }" : "=r"(a) : "l"(p));
    return a;
}
#define CP_ASYNC16(dst, src) \
    asm volatile("cp.async.cg.shared.global [%0], [%1], 16;" :: "r"(dst), "l"(src) : "memory")
#define CP_COMMIT() asm volatile("cp.async.commit_group;" ::: "memory")
#define CP_WAIT(n)  asm volatile("cp.async.wait_group %0;" :: "n"(n) : "memory")

// m16n8k16 bf16 mma: D += A*B, fp32 accum
__device__ __forceinline__ void mma_bf16(float* d, const uint32_t* a, const uint32_t* b) {
    asm volatile(
        "mma.sync.aligned.m16n8k16.row.col.f32.bf16.bf16.f32 "
        "{%0,%1,%2,%3}, {%4,%5,%6,%7}, {%8,%9}, {%0,%1,%2,%3};"
        : "+f"(d[0]), "+f"(d[1]), "+f"(d[2]), "+f"(d[3])
        : "r"(a[0]), "r"(a[1]), "r"(a[2]), "r"(a[3]), "r"(b[0]), "r"(b[1]));
}
#define LDMATRIX_X4(r0, r1, r2, r3, addr) \
    asm volatile("ldmatrix.sync.aligned.m8n8.x4.shared.b16 {%0,%1,%2,%3}, [%4];" \
        : "=r"(r0), "=r"(r1), "=r"(r2), "=r"(r3) : "r"(addr))

// ---------------------------------------------------------------------------
// colsum / rinv
// ---------------------------------------------------------------------------
__global__ void zero_colsum_kernel() {
    int i = blockIdx.x * blockDim.x + threadIdx.x;
    if (i < V) g_colsum[i] = 0.0f;
}
__global__ void __launch_bounds__(256) colsum_partial_kernel(const float* __restrict__ adj) {
    int j  = blockIdx.x * 256 + threadIdx.x;
    int i0 = blockIdx.y * 64;
    float s = 0.0f;
#pragma unroll 8
    for (int i = 0; i < 64; i++) s += adj[(size_t)(i0 + i) * V + j];
    atomicAdd(&g_colsum[j], s);
}
__global__ void finalize_rinv_kernel() {
    int i = blockIdx.x * blockDim.x + threadIdx.x;
    if (i < V) g_rinv[i] = rsqrtf(g_colsum[i]);
}

// ---------------------------------------------------------------------------
// transpose: adjT[j][v] = bf16(adj[v][j] * rinv[v])
// ---------------------------------------------------------------------------
__global__ void __launch_bounds__(256) transpose_kernel(const float* __restrict__ adj) {
    __shared__ float t[32][33];
    int tx = threadIdx.x & 31, ty = threadIdx.x >> 5;
    int j0 = blockIdx.x * 32, v0 = blockIdx.y * 32;
#pragma unroll
    for (int i = 0; i < 4; i++) {
        int vy = ty + i * 8;
        t[vy][tx] = adj[(size_t)(v0 + vy) * V + j0 + tx];
    }
    __syncthreads();
    float rv = g_rinv[v0 + tx];
#pragma unroll
    for (int i = 0; i < 4; i++) {
        int jy = ty + i * 8;
        g_adjT[(size_t)(j0 + jy) * V + v0 + tx] = __float2bfloat16_rn(t[tx][jy] * rv);
    }
}

// ---------------------------------------------------------------------------
// project (tensor-core): xT[(ab*64+d)][v] = bf16( sum_k x[ab,v,k] * W[k,d] )
// CTA: 128 v-rows of one ab, 8 warps, warp m-tile 16. W-frags prebuilt from
// fp32 smem; x staged fp32->bf16 into smem, A-frags via ldmatrix.
// ---------------------------------------------------------------------------
#define PJ_WST   68                  // Wf stride (floats)
#define PJ_XST   72                  // Xs stride (halves), 144B: ldmatrix bank-free
#define PJ_YST   136                 // Ys stride (halves): v 128 + 8 pad
#define PJ_WF_BYTES (DIN * PJ_WST * 4)          // 17408
#define PJ_XS_BYTES (128 * PJ_XST * 2)          // 18432 (Ys 64*136*2=17408 aliases)

__global__ void __launch_bounds__(256) project_mma_kernel(const float* __restrict__ x,
                                                          const float* __restrict__ w) {
    __shared__ __align__(16) char smem_raw[PJ_WF_BYTES + PJ_XS_BYTES];
    float* Wf = (float*)smem_raw;
    __nv_bfloat16* Xs = (__nv_bfloat16*)(smem_raw + PJ_WF_BYTES);
    __nv_bfloat16* Ys = Xs;   // reused after mma loop (post-sync)

    int tid  = threadIdx.x;
    int wid  = tid >> 5, lane = tid & 31;
    int lg   = lane >> 2, lc = lane & 3;
    int ab   = blockIdx.y;
    int v0   = blockIdx.x * 128;

    // load W fp32 -> Wf (64x64, stride 68)
#pragma unroll
    for (int s = tid; s < 1024; s += 256) {
        int k = s >> 4, dq = s & 15;
        *(float4*)&Wf[k * PJ_WST + dq * 4] = *(const float4*)&w[k * DOUT + dq * 4];
    }
    // load x rows v0..v0+127, convert to bf16 into Xs
    {
        const float* xb = x + ((size_t)ab * V + v0) * DIN;
#pragma unroll
        for (int s = tid; s < 2048; s += 256) {
            int r = s >> 4, kq = s & 15;
            float4 f = *(const float4*)&xb[(size_t)r * DIN + kq * 4];
            __nv_bfloat162 h0 = __floats2bfloat162_rn(f.x, f.y);
            __nv_bfloat162 h1 = __floats2bfloat162_rn(f.z, f.w);
            *(uint2*)&Xs[r * PJ_XST + kq * 4] = make_uint2(*(uint32_t*)&h0, *(uint32_t*)&h1);
        }
    }
    __syncthreads();

    // prebuild B frags: b[k16][fj][2], lane(g,t): low=W[kb+2t][n], high=W[kb+2t+1][n]
    uint32_t b[4][8][2];
#pragma unroll
    for (int k16 = 0; k16 < 4; k16++) {
#pragma unroll
        for (int fj = 0; fj < 8; fj++) {
            int n  = fj * 8 + lg;
            int k0 = k16 * 16 + lc * 2;
            int k1 = k0 + 8;
            __nv_bfloat162 p0 = __floats2bfloat162_rn(Wf[k0 * PJ_WST + n], Wf[(k0 + 1) * PJ_WST + n]);
            __nv_bfloat162 p1 = __floats2bfloat162_rn(Wf[k1 * PJ_WST + n], Wf[(k1 + 1) * PJ_WST + n]);
            b[k16][fj][0] = *(uint32_t*)&p0;
            b[k16][fj][1] = *(uint32_t*)&p1;
        }
    }

    float d[8][4];
#pragma unroll
    for (int j = 0; j < 8; j++)
#pragma unroll
        for (int q = 0; q < 4; q++) d[j][q] = 0.0f;

    // A-frag ldmatrix lane address (rows = lane&15, k-half = (lane>>4)*8)
    uint32_t xs_base = smem_u32(Xs);
    int r_a = lane & 15, ka = (lane >> 4) * 8;
    uint32_t a_addr0 = xs_base + (uint32_t)((wid * 16 + r_a) * PJ_XST + ka) * 2u;

#pragma unroll
    for (int k16 = 0; k16 < 4; k16++) {
        uint32_t a[4];
        LDMATRIX_X4(a[0], a[1], a[2], a[3], a_addr0 + (uint32_t)(k16 * 16 * 2));
#pragma unroll
        for (int fj = 0; fj < 8; fj++) mma_bf16(d[fj], a, b[k16][fj]);
    }
    __syncthreads();   // all Xs reads done; reuse as Ys

    // bounce accums through smem transposed: Ys[n][v], n=0..63, v=0..127
#pragma unroll
    for (int fj = 0; fj < 8; fj++) {
        int n    = fj * 8 + lc * 2;
        int vlo  = wid * 16 + lg;
        int vhi  = vlo + 8;
        Ys[n * PJ_YST + vlo]       = __float2bfloat16_rn(d[fj][0]);
        Ys[(n + 1) * PJ_YST + vlo] = __float2bfloat16_rn(d[fj][1]);
        Ys[n * PJ_YST + vhi]       = __float2bfloat16_rn(d[fj][2]);
        Ys[(n + 1) * PJ_YST + vhi] = __float2bfloat16_rn(d[fj][3]);
    }
    __syncthreads();

    // coalesced write: 64 c-rows x 128 v halves
#pragma unroll
    for (int s = tid; s < 1024; s += 256) {
        int n = s >> 4, vq = s & 15;
        uint4 val = *(uint4*)&Ys[n * PJ_YST + vq * 8];
        *(uint4*)&g_xT[(size_t)(ab * 64 + n) * V + v0 + vq * 8] = val;
    }
}

// ---------------------------------------------------------------------------
// agg: mma.sync bf16 GEMM  D[j, c] = sum_v adjT[j,v] * xT[c,v]
//   CTA tile 128(j) x 256(c), 8 warps, warp tile 64x64
//   KC=128, double-buffered cp.async; fragments via ldmatrix.x4
//   smem row stride 136 halves (272B: 16B-aligned, ldmatrix bank-free)
// ---------------------------------------------------------------------------
#define MT 128
#define NT 256
#define KC 128
#define NCHUNK (V / KC)               // 16
#define LDS_STRIDE 136                // halves per row (272 B)
#define A_HALVES (MT * LDS_STRIDE)    // 17408
#define B_HALVES (NT * LDS_STRIDE)    // 34816
#define SM_BYTES ((2 * A_HALVES + 2 * B_HALVES) * 2)   // 208896 B

__device__ __forceinline__ void load_chunk(uint32_t smem_base, int buf,
                                           int j0, int n0, int k0, int tid) {
    uint32_t sa = smem_base + (uint32_t)(buf * A_HALVES) * 2u;
    uint32_t sb = smem_base + (uint32_t)(2 * A_HALVES + buf * B_HALVES) * 2u;
    // A: 128 rows x 256B = 2048 16B-segs (8/thread)
#pragma unroll
    for (int q = 0; q < 8; q++) {
        int s = tid + q * 256;
        int r = s >> 4, o = s & 15;
        uint32_t dst = sa + (uint32_t)(r * LDS_STRIDE + o * 8) * 2u;
        CP_ASYNC16(dst, &g_adjT[(size_t)(j0 + r) * V + k0 + o * 8]);
    }
    // B: 256 rows x 256B = 4096 16B-segs (16/thread)
#pragma unroll
    for (int q = 0; q < 16; q++) {
        int s = tid + q * 256;
        int r = s >> 4, o = s & 15;
        uint32_t dst = sb + (uint32_t)(r * LDS_STRIDE + o * 8) * 2u;
        CP_ASYNC16(dst, &g_xT[(size_t)(n0 + r) * V + k0 + o * 8]);
    }
}

__global__ void __launch_bounds__(256, 1) agg_mma_kernel(const float* __restrict__ bias,
                                                         float* __restrict__ out) {
    extern __shared__ __align__(16) __nv_bfloat16 smem[];
    uint32_t smem_base = smem_u32(smem);
    int tid  = threadIdx.x;
    int wid  = tid >> 5, lane = tid & 31;
    int j0   = blockIdx.x * MT;
    int n0   = blockIdx.y * NT;
    int m0w  = (wid & 1) * 64;
    int n0w  = (wid >> 1) * 64;
    int lg   = lane >> 2, lc = lane & 3;

    // ldmatrix lane offsets
    int r_a   = lane & 15;                              // A: row within 16
    int ka    = (lane >> 4) * 8;                        // A: k half
    int n_off = (lane & 7) + ((lane >> 4) & 1) * 8;     // B: n within 16
    int k_off = ((lane >> 3) & 1) * 8;                  // B: k half

    float d[4][8][4];
#pragma unroll
    for (int i = 0; i < 4; i++)
#pragma unroll
        for (int j = 0; j < 8; j++)
#pragma unroll
            for (int q = 0; q < 4; q++) d[i][j][q] = 0.0f;

    load_chunk(smem_base, 0, j0, n0, 0, tid);   CP_COMMIT();
    load_chunk(smem_base, 1, j0, n0, KC, tid);  CP_COMMIT();

    for (int i = 0; i < NCHUNK; i++) {
        if (i < NCHUNK - 1) { CP_WAIT(1); } else { CP_WAIT(0); }
        __syncthreads();

        int buf = i & 1;
        uint32_t As = smem_base + (uint32_t)(buf * A_HALVES) * 2u;
        uint32_t Bs = smem_base + (uint32_t)(2 * A_HALVES + buf * B_HALVES) * 2u;
        uint32_t a_base = As + (uint32_t)((m0w + r_a) * LDS_STRIDE + ka) * 2u;
        uint32_t b_base = Bs + (uint32_t)((n0w + n_off) * LDS_STRIDE + k_off) * 2u;

#pragma unroll
        for (int k16 = 0; k16 < 8; k16++) {
            uint32_t kb2 = (uint32_t)(k16 * 16 * 2);
            uint32_t a[4][4], b[8][2];
#pragma unroll
            for (int fi = 0; fi < 4; fi++) {
                LDMATRIX_X4(a[fi][0], a[fi][1], a[fi][2], a[fi][3],
                            a_base + (uint32_t)(fi * 16 * LDS_STRIDE * 2) + kb2);
            }
#pragma unroll
            for (int p = 0; p < 4; p++) {
                LDMATRIX_X4(b[2 * p][0], b[2 * p][1], b[2 * p + 1][0], b[2 * p + 1][1],
                            b_base + (uint32_t)(p * 16 * LDS_STRIDE * 2) + kb2);
            }
#pragma unroll
            for (int fi = 0; fi < 4; fi++)
#pragma unroll
                for (int fj = 0; fj < 8; fj++)
                    mma_bf16(d[fi][fj], a[fi], b[fj]);
        }
        __syncthreads();

        if (i + 2 < NCHUNK) {
            load_chunk(smem_base, buf, j0, n0, (i + 2) * KC, tid);
            CP_COMMIT();
        }
    }

    // epilogue
#pragma unroll
    for (int fi = 0; fi < 4; fi++) {
        int row_lo = j0 + m0w + fi * 16 + lg;
        int row_hi = row_lo + 8;
        float rlo = g_rinv[row_lo];
        float rhi = g_rinv[row_hi];
#pragma unroll
        for (int fj = 0; fj < 8; fj++) {
            int c  = n0 + n0w + fj * 8 + lc * 2;
            int ab = c >> 6;
            int dd = c & 63;
            float2 bi = *(const float2*)&bias[dd];
            float2 olo, ohi;
            olo.x = fmaxf(bi.x + rlo * d[fi][fj][0], 0.0f);
            olo.y = fmaxf(bi.y + rlo * d[fi][fj][1], 0.0f);
            ohi.x = fmaxf(bi.x + rhi * d[fi][fj][2], 0.0f);
            ohi.y = fmaxf(bi.y + rhi * d[fi][fj][3], 0.0f);
            *(float2*)&out[((size_t)ab * V + row_lo) * DOUT + dd] = olo;
            *(float2*)&out[((size_t)ab * V + row_hi) * DOUT + dd] = ohi;
        }
    }
}

// ---------------------------------------------------------------------------
extern "C" void kernel_launch(void* const* d_in, const int* in_sizes, int n_in,
                              void* d_out, int out_size) {
    const float* adj  = (const float*)d_in[0];
    const float* x    = (const float*)d_in[1];
    const float* w    = (const float*)d_in[2];
    const float* bias = (const float*)d_in[3];
    float* out        = (float*)d_out;

    cudaFuncSetAttribute(agg_mma_kernel, cudaFuncAttributeMaxDynamicSharedMemorySize, SM_BYTES);

    zero_colsum_kernel<<<8, 256>>>();
    colsum_partial_kernel<<<dim3(8, 32), 256>>>(adj);
    finalize_rinv_kernel<<<8, 256>>>();
    transpose_kernel<<<dim3(64, 64), 256>>>(adj);
    project_mma_kernel<<<dim3(V / 128, NB), 256>>>(x, w);
    agg_mma_kernel<<<dim3(V / MT, NCOL / NT), 256, SM_BYTES>>>(bias, out);
}

// round 8
// speedup vs baseline: 6.1189x; 1.0753x over previous
#include <cuda_runtime.h>
#include <cuda_bf16.h>
#include <cstdint>

#define V     2048
#define DIN   64
#define DOUT  64
#define NB    64            // A*B = 8*8
#define NCOL  (NB * DOUT)   // 4096 columns of the big GEMM

// ---------------- scratch (device globals; no cudaMalloc allowed) ----------
__device__ __nv_bfloat16 g_adjT[(size_t)V * V];   // 8 MB: adjT[j][v] = bf16(adj[v][j]*rinv[v])
__device__ __nv_bfloat16 g_xT[(size_t)NCOL * V];  // 16 MB: xT[c][v] = bf16((x@W)[ab,v,d])
__device__ float g_part[32][V];                   // colsum partials (overwritten fully each run)
__device__ float g_rinv[V];

// ---------------- helpers ---------------------------------------------------
__device__ __forceinline__ uint32_t smem_u32(const void* p) {
    uint32_t a;
    asm("{ .reg .u64 t; cvta.to.shared.u64 t, %1; cvt.u32.u64 %0, t; }" : "=r"(a) : "l"(p));
    return a;
}
#define CP_ASYNC16(dst, src) \
    asm volatile("cp.async.cg.shared.global [%0], [%1], 16;" :: "r"(dst), "l"(src) : "memory")
#define CP_COMMIT() asm volatile("cp.async.commit_group;" ::: "memory")
#define CP_WAIT(n)  asm volatile("cp.async.wait_group %0;" :: "n"(n) : "memory")

// m16n8k16 bf16 mma: D += A*B, fp32 accum
__device__ __forceinline__ void mma_bf16(float* d, const uint32_t* a, const uint32_t* b) {
    asm volatile(
        "mma.sync.aligned.m16n8k16.row.col.f32.bf16.bf16.f32 "
        "{%0,%1,%2,%3}, {%4,%5,%6,%7}, {%8,%9}, {%0,%1,%2,%3};"
        : "+f"(d[0]), "+f"(d[1]), "+f"(d[2]), "+f"(d[3])
        : "r"(a[0]), "r"(a[1]), "r"(a[2]), "r"(a[3]), "r"(b[0]), "r"(b[1]));
}
#define LDMATRIX_X4(r0, r1, r2, r3, addr) \
    asm volatile("ldmatrix.sync.aligned.m8n8.x4.shared.b16 {%0,%1,%2,%3}, [%4];" \
        : "=r"(r0), "=r"(r1), "=r"(r2), "=r"(r3) : "r"(addr))

// ---------------------------------------------------------------------------
// colsum partials (no atomics, no zeroing): g_part[by][j] = sum of 64 rows
// ---------------------------------------------------------------------------
__global__ void __launch_bounds__(256) colsum_partial_kernel(const float* __restrict__ adj) {
    int j  = blockIdx.x * 256 + threadIdx.x;
    int i0 = blockIdx.y * 64;
    float s = 0.0f;
#pragma unroll 8
    for (int i = 0; i < 64; i++) s += adj[(size_t)(i0 + i) * V + j];
    g_part[blockIdx.y][j] = s;
}
// reduce 32 partials -> rinv
__global__ void finalize_rinv_kernel() {
    int j = blockIdx.x * blockDim.x + threadIdx.x;
    float s = 0.0f;
#pragma unroll
    for (int i = 0; i < 32; i++) s += g_part[i][j];
    g_rinv[j] = rsqrtf(s);
}

// ---------------------------------------------------------------------------
// transpose: adjT[j][v] = bf16(adj[v][j] * rinv[v]);  64x64 tiles
// ---------------------------------------------------------------------------
__global__ void __launch_bounds__(256) transpose_kernel(const float* __restrict__ adj) {
    __shared__ float ts[64][65];   // ts[j][v]
    __shared__ float rs[64];
    int tid = threadIdx.x;
    int j0 = blockIdx.x * 64, v0 = blockIdx.y * 64;

    // load 64 v-rows x 64 j-cols; scatter-transpose into ts[j][v]
#pragma unroll
    for (int p = 0; p < 4; p++) {
        int r = p * 16 + (tid >> 4);       // v row
        int c = (tid & 15) * 4;            // j col
        float4 f = *(const float4*)&adj[(size_t)(v0 + r) * V + j0 + c];
        ts[c + 0][r] = f.x;
        ts[c + 1][r] = f.y;
        ts[c + 2][r] = f.z;
        ts[c + 3][r] = f.w;
    }
    if (tid < 64) rs[tid] = g_rinv[v0 + tid];
    __syncthreads();

    // store: 128B per j-row (8 threads x uint4 of 8 bf16)
#pragma unroll
    for (int p = 0; p < 2; p++) {
        int jr = p * 32 + (tid >> 3);
        int vo = (tid & 7) * 8;
        __nv_bfloat16 h[8];
#pragma unroll
        for (int i = 0; i < 8; i++)
            h[i] = __float2bfloat16_rn(ts[jr][vo + i] * rs[vo + i]);
        *(uint4*)&g_adjT[(size_t)(j0 + jr) * V + v0 + vo] = *(uint4*)h;
    }
}

// ---------------------------------------------------------------------------
// project (tensor-core): xT[(ab*64+d)][v] = bf16( sum_k x[ab,v,k] * W[k,d] )
// ---------------------------------------------------------------------------
#define PJ_WST   68
#define PJ_XST   72
#define PJ_YST   136
#define PJ_WF_BYTES (DIN * PJ_WST * 4)
#define PJ_XS_BYTES (128 * PJ_XST * 2)

__global__ void __launch_bounds__(256) project_mma_kernel(const float* __restrict__ x,
                                                          const float* __restrict__ w) {
    __shared__ __align__(16) char smem_raw[PJ_WF_BYTES + PJ_XS_BYTES];
    float* Wf = (float*)smem_raw;
    __nv_bfloat16* Xs = (__nv_bfloat16*)(smem_raw + PJ_WF_BYTES);
    __nv_bfloat16* Ys = Xs;

    int tid  = threadIdx.x;
    int wid  = tid >> 5, lane = tid & 31;
    int lg   = lane >> 2, lc = lane & 3;
    int ab   = blockIdx.y;
    int v0   = blockIdx.x * 128;

#pragma unroll
    for (int s = tid; s < 1024; s += 256) {
        int k = s >> 4, dq = s & 15;
        *(float4*)&Wf[k * PJ_WST + dq * 4] = *(const float4*)&w[k * DOUT + dq * 4];
    }
    {
        const float* xb = x + ((size_t)ab * V + v0) * DIN;
#pragma unroll
        for (int s = tid; s < 2048; s += 256) {
            int r = s >> 4, kq = s & 15;
            float4 f = *(const float4*)&xb[(size_t)r * DIN + kq * 4];
            __nv_bfloat162 h0 = __floats2bfloat162_rn(f.x, f.y);
            __nv_bfloat162 h1 = __floats2bfloat162_rn(f.z, f.w);
            *(uint2*)&Xs[r * PJ_XST + kq * 4] = make_uint2(*(uint32_t*)&h0, *(uint32_t*)&h1);
        }
    }
    __syncthreads();

    uint32_t b[4][8][2];
#pragma unroll
    for (int k16 = 0; k16 < 4; k16++) {
#pragma unroll
        for (int fj = 0; fj < 8; fj++) {
            int n  = fj * 8 + lg;
            int k0 = k16 * 16 + lc * 2;
            int k1 = k0 + 8;
            __nv_bfloat162 p0 = __floats2bfloat162_rn(Wf[k0 * PJ_WST + n], Wf[(k0 + 1) * PJ_WST + n]);
            __nv_bfloat162 p1 = __floats2bfloat162_rn(Wf[k1 * PJ_WST + n], Wf[(k1 + 1) * PJ_WST + n]);
            b[k16][fj][0] = *(uint32_t*)&p0;
            b[k16][fj][1] = *(uint32_t*)&p1;
        }
    }

    float d[8][4];
#pragma unroll
    for (int j = 0; j < 8; j++)
#pragma unroll
        for (int q = 0; q < 4; q++) d[j][q] = 0.0f;

    uint32_t xs_base = smem_u32(Xs);
    int r_a = lane & 15, ka = (lane >> 4) * 8;
    uint32_t a_addr0 = xs_base + (uint32_t)((wid * 16 + r_a) * PJ_XST + ka) * 2u;

#pragma unroll
    for (int k16 = 0; k16 < 4; k16++) {
        uint32_t a[4];
        LDMATRIX_X4(a[0], a[1], a[2], a[3], a_addr0 + (uint32_t)(k16 * 16 * 2));
#pragma unroll
        for (int fj = 0; fj < 8; fj++) mma_bf16(d[fj], a, b[k16][fj]);
    }
    __syncthreads();

#pragma unroll
    for (int fj = 0; fj < 8; fj++) {
        int n    = fj * 8 + lc * 2;
        int vlo  = wid * 16 + lg;
        int vhi  = vlo + 8;
        Ys[n * PJ_YST + vlo]       = __float2bfloat16_rn(d[fj][0]);
        Ys[(n + 1) * PJ_YST + vlo] = __float2bfloat16_rn(d[fj][1]);
        Ys[n * PJ_YST + vhi]       = __float2bfloat16_rn(d[fj][2]);
        Ys[(n + 1) * PJ_YST + vhi] = __float2bfloat16_rn(d[fj][3]);
    }
    __syncthreads();

#pragma unroll
    for (int s = tid; s < 1024; s += 256) {
        int n = s >> 4, vq = s & 15;
        uint4 val = *(uint4*)&Ys[n * PJ_YST + vq * 8];
        *(uint4*)&g_xT[(size_t)(ab * 64 + n) * V + v0 + vq * 8] = val;
    }
}

// ---------------------------------------------------------------------------
// agg: mma.sync bf16 GEMM, CTA 128x256, 8 warps (warp 64x64)
// KC=64, 3-stage cp.async pipeline, ONE __syncthreads per chunk
// ---------------------------------------------------------------------------
#define MT 128
#define NT 256
#define KC 64
#define NCHUNK (V / KC)               // 32
#define LDS_STRIDE 72                 // halves per row (144 B, ldmatrix bank-free)
#define A_HALVES (MT * LDS_STRIDE)    // 9216
#define B_HALVES (NT * LDS_STRIDE)    // 18432
#define ST_HALVES (A_HALVES + B_HALVES)           // per stage
#define SM_BYTES (3 * ST_HALVES * 2)              // 165888 B

__device__ __forceinline__ void load_chunk(uint32_t smem_base, int stage,
                                           int j0, int n0, int k0, int tid) {
    uint32_t sa = smem_base + (uint32_t)(stage * ST_HALVES) * 2u;
    uint32_t sb = sa + (uint32_t)A_HALVES * 2u;
    // A: 128 rows x 128B = 1024 16B-segs (4/thread)
#pragma unroll
    for (int q = 0; q < 4; q++) {
        int s = tid + q * 256;
        int r = s >> 3, o = s & 7;
        uint32_t dst = sa + (uint32_t)(r * LDS_STRIDE + o * 8) * 2u;
        CP_ASYNC16(dst, &g_adjT[(size_t)(j0 + r) * V + k0 + o * 8]);
    }
    // B: 256 rows x 128B = 2048 16B-segs (8/thread)
#pragma unroll
    for (int q = 0; q < 8; q++) {
        int s = tid + q * 256;
        int r = s >> 3, o = s & 7;
        uint32_t dst = sb + (uint32_t)(r * LDS_STRIDE + o * 8) * 2u;
        CP_ASYNC16(dst, &g_xT[(size_t)(n0 + r) * V + k0 + o * 8]);
    }
}

__global__ void __launch_bounds__(256, 1) agg_mma_kernel(const float* __restrict__ bias,
                                                         float* __restrict__ out) {
    extern __shared__ __align__(16) __nv_bfloat16 smem[];
    uint32_t smem_base = smem_u32(smem);
    int tid  = threadIdx.x;
    int wid  = tid >> 5, lane = tid & 31;
    int j0   = blockIdx.x * MT;
    int n0   = blockIdx.y * NT;
    int m0w  = (wid & 1) * 64;
    int n0w  = (wid >> 1) * 64;
    int lg   = lane >> 2, lc = lane & 3;

    int r_a   = lane & 15;
    int ka    = (lane >> 4) * 8;
    int n_off = (lane & 7) + ((lane >> 4) & 1) * 8;
    int k_off = ((lane >> 3) & 1) * 8;

    float d[4][8][4];
#pragma unroll
    for (int i = 0; i < 4; i++)
#pragma unroll
        for (int j = 0; j < 8; j++)
#pragma unroll
            for (int q = 0; q < 4; q++) d[i][j][q] = 0.0f;

    load_chunk(smem_base, 0, j0, n0, 0, tid);   CP_COMMIT();
    load_chunk(smem_base, 1, j0, n0, KC, tid);  CP_COMMIT();

    for (int i = 0; i < NCHUNK; i++) {
        if (i < NCHUNK - 1) { CP_WAIT(1); } else { CP_WAIT(0); }
        __syncthreads();   // chunk i resident; also releases stage (i-1)%3 for reuse

        int stage = i % 3;
        uint32_t As = smem_base + (uint32_t)(stage * ST_HALVES) * 2u;
        uint32_t Bs = As + (uint32_t)A_HALVES * 2u;
        uint32_t a_base = As + (uint32_t)((m0w + r_a) * LDS_STRIDE + ka) * 2u;
        uint32_t b_base = Bs + (uint32_t)((n0w + n_off) * LDS_STRIDE + k_off) * 2u;

#pragma unroll
        for (int k16 = 0; k16 < 4; k16++) {
            uint32_t kb2 = (uint32_t)(k16 * 16 * 2);
            uint32_t a[4][4], b[8][2];
#pragma unroll
            for (int fi = 0; fi < 4; fi++) {
                LDMATRIX_X4(a[fi][0], a[fi][1], a[fi][2], a[fi][3],
                            a_base + (uint32_t)(fi * 16 * LDS_STRIDE * 2) + kb2);
            }
#pragma unroll
            for (int p = 0; p < 4; p++) {
                LDMATRIX_X4(b[2 * p][0], b[2 * p][1], b[2 * p + 1][0], b[2 * p + 1][1],
                            b_base + (uint32_t)(p * 16 * LDS_STRIDE * 2) + kb2);
            }
#pragma unroll
            for (int fi = 0; fi < 4; fi++)
#pragma unroll
                for (int fj = 0; fj < 8; fj++)
                    mma_bf16(d[fi][fj], a[fi], b[fj]);
        }
        // no second barrier: 3-stage ring — load (i+2) targets stage (i+2)%3,
        // last computed in iter i-1, protected by the barrier above.
        if (i + 2 < NCHUNK) {
            load_chunk(smem_base, (i + 2) % 3, j0, n0, (i + 2) * KC, tid);
            CP_COMMIT();
        }
    }

    // epilogue
#pragma unroll
    for (int fi = 0; fi < 4; fi++) {
        int row_lo = j0 + m0w + fi * 16 + lg;
        int row_hi = row_lo + 8;
        float rlo = g_rinv[row_lo];
        float rhi = g_rinv[row_hi];
#pragma unroll
        for (int fj = 0; fj < 8; fj++) {
            int c  = n0 + n0w + fj * 8 + lc * 2;
            int ab = c >> 6;
            int dd = c & 63;
            float2 bi = *(const float2*)&bias[dd];
            float2 olo, ohi;
            olo.x = fmaxf(bi.x + rlo * d[fi][fj][0], 0.0f);
            olo.y = fmaxf(bi.y + rlo * d[fi][fj][1], 0.0f);
            ohi.x = fmaxf(bi.x + rhi * d[fi][fj][2], 0.0f);
            ohi.y = fmaxf(bi.y + rhi * d[fi][fj][3], 0.0f);
            *(float2*)&out[((size_t)ab * V + row_lo) * DOUT + dd] = olo;
            *(float2*)&out[((size_t)ab * V + row_hi) * DOUT + dd] = ohi;
        }
    }
}

// ---------------------------------------------------------------------------
extern "C" void kernel_launch(void* const* d_in, const int* in_sizes, int n_in,
                              void* d_out, int out_size) {
    const float* adj  = (const float*)d_in[0];
    const float* x    = (const float*)d_in[1];
    const float* w    = (const float*)d_in[2];
    const float* bias = (const float*)d_in[3];
    float* out        = (float*)d_out;

    cudaFuncSetAttribute(agg_mma_kernel, cudaFuncAttributeMaxDynamicSharedMemorySize, SM_BYTES);

    colsum_partial_kernel<<<dim3(8, 32), 256>>>(adj);
    finalize_rinv_kernel<<<8, 256>>>();
    transpose_kernel<<<dim3(32, 32), 256>>>(adj);
    project_mma_kernel<<<dim3(V / 128, NB), 256>>>(x, w);
    agg_mma_kernel<<<dim3(V / MT, NCOL / NT), 256, SM_BYTES>>>(bias, out);
}

// round 11
// speedup vs baseline: 6.3398x; 1.0361x over previous
#include <cuda_runtime.h>
#include <cuda_bf16.h>
#include <cstdint>

#define V     2048
#define DIN   64
#define DOUT  64
#define NB    64            // A*B = 8*8
#define NCOL  (NB * DOUT)   // 4096 columns of the big GEMM

// ---------------- scratch (device globals; no cudaMalloc allowed) ----------
__device__ __nv_bfloat16 g_adjT[(size_t)V * V];   // 8 MB: adjT[j][v] = bf16(adj[v][j]*rinv[v])
__device__ __nv_bfloat16 g_xT[(size_t)NCOL * V];  // 16 MB: xT[c][v] = bf16((x@W)[ab,v,d])
__device__ float g_part[32][V];                   // colsum partials (overwritten fully each run)
__device__ float g_rinv[V];

// ---------------- helpers ---------------------------------------------------
__device__ __forceinline__ uint32_t smem_u32(const void* p) {
    uint32_t a;
    asm("{ .reg .u64 t; cvta.to.shared.u64 t, %1; cvt.u32.u64 %0, t; }" : "=r"(a) : "l"(p));
    return a;
}
#define CP_ASYNC16(dst, src) \
    asm volatile("cp.async.cg.shared.global [%0], [%1], 16;" :: "r"(dst), "l"(src) : "memory")
#define CP_COMMIT() asm volatile("cp.async.commit_group;" ::: "memory")
#define CP_WAIT(n)  asm volatile("cp.async.wait_group %0;" :: "n"(n) : "memory")

// m16n8k16 bf16 mma: D += A*B, fp32 accum
__device__ __forceinline__ void mma_bf16(float* d, const uint32_t* a, const uint32_t* b) {
    asm volatile(
        "mma.sync.aligned.m16n8k16.row.col.f32.bf16.bf16.f32 "
        "{%0,%1,%2,%3}, {%4,%5,%6,%7}, {%8,%9}, {%0,%1,%2,%3};"
        : "+f"(d[0]), "+f"(d[1]), "+f"(d[2]), "+f"(d[3])
        : "r"(a[0]), "r"(a[1]), "r"(a[2]), "r"(a[3]), "r"(b[0]), "r"(b[1]));
}
#define LDMATRIX_X4(r0, r1, r2, r3, addr) \
    asm volatile("ldmatrix.sync.aligned.m8n8.x4.shared.b16 {%0,%1,%2,%3}, [%4];" \
        : "=r"(r0), "=r"(r1), "=r"(r2), "=r"(r3) : "r"(addr))

// ---------------------------------------------------------------------------
// colsum partials (no atomics, no zeroing): g_part[by][j] = sum of 64 rows
// ---------------------------------------------------------------------------
__global__ void __launch_bounds__(256) colsum_partial_kernel(const float* __restrict__ adj) {
    int j  = blockIdx.x * 256 + threadIdx.x;
    int i0 = blockIdx.y * 64;
    float s = 0.0f;
#pragma unroll 8
    for (int i = 0; i < 64; i++) s += adj[(size_t)(i0 + i) * V + j];
    g_part[blockIdx.y][j] = s;
}
__global__ void finalize_rinv_kernel() {
    int j = blockIdx.x * blockDim.x + threadIdx.x;
    float s = 0.0f;
#pragma unroll
    for (int i = 0; i < 32; i++) s += g_part[i][j];
    g_rinv[j] = rsqrtf(s);
}

// ---------------------------------------------------------------------------
// transpose: adjT[j][v] = bf16(adj[v][j] * rinv[v]);  64x64 tiles
// ---------------------------------------------------------------------------
__global__ void __launch_bounds__(256) transpose_kernel(const float* __restrict__ adj) {
    __shared__ float ts[64][65];   // ts[j][v]
    __shared__ float rs[64];
    int tid = threadIdx.x;
    int j0 = blockIdx.x * 64, v0 = blockIdx.y * 64;

#pragma unroll
    for (int p = 0; p < 4; p++) {
        int r = p * 16 + (tid >> 4);
        int c = (tid & 15) * 4;
        float4 f = *(const float4*)&adj[(size_t)(v0 + r) * V + j0 + c];
        ts[c + 0][r] = f.x;
        ts[c + 1][r] = f.y;
        ts[c + 2][r] = f.z;
        ts[c + 3][r] = f.w;
    }
    if (tid < 64) rs[tid] = g_rinv[v0 + tid];
    __syncthreads();

#pragma unroll
    for (int p = 0; p < 2; p++) {
        int jr = p * 32 + (tid >> 3);
        int vo = (tid & 7) * 8;
        __nv_bfloat16 h[8];
#pragma unroll
        for (int i = 0; i < 8; i++)
            h[i] = __float2bfloat16_rn(ts[jr][vo + i] * rs[vo + i]);
        *(uint4*)&g_adjT[(size_t)(j0 + jr) * V + v0 + vo] = *(uint4*)h;
    }
}

// ---------------------------------------------------------------------------
// project (tensor-core): xT[(ab*64+d)][v] = bf16( sum_k x[ab,v,k] * W[k,d] )
// ---------------------------------------------------------------------------
#define PJ_WST   68
#define PJ_XST   72
#define PJ_YST   136
#define PJ_WF_BYTES (DIN * PJ_WST * 4)
#define PJ_XS_BYTES (128 * PJ_XST * 2)

__global__ void __launch_bounds__(256) project_mma_kernel(const float* __restrict__ x,
                                                          const float* __restrict__ w) {
    __shared__ __align__(16) char smem_raw[PJ_WF_BYTES + PJ_XS_BYTES];
    float* Wf = (float*)smem_raw;
    __nv_bfloat16* Xs = (__nv_bfloat16*)(smem_raw + PJ_WF_BYTES);
    __nv_bfloat16* Ys = Xs;

    int tid  = threadIdx.x;
    int wid  = tid >> 5, lane = tid & 31;
    int lg   = lane >> 2, lc = lane & 3;
    int ab   = blockIdx.y;
    int v0   = blockIdx.x * 128;

#pragma unroll
    for (int s = tid; s < 1024; s += 256) {
        int k = s >> 4, dq = s & 15;
        *(float4*)&Wf[k * PJ_WST + dq * 4] = *(const float4*)&w[k * DOUT + dq * 4];
    }
    {
        const float* xb = x + ((size_t)ab * V + v0) * DIN;
#pragma unroll
        for (int s = tid; s < 2048; s += 256) {
            int r = s >> 4, kq = s & 15;
            float4 f = *(const float4*)&xb[(size_t)r * DIN + kq * 4];
            __nv_bfloat162 h0 = __floats2bfloat162_rn(f.x, f.y);
            __nv_bfloat162 h1 = __floats2bfloat162_rn(f.z, f.w);
            *(uint2*)&Xs[r * PJ_XST + kq * 4] = make_uint2(*(uint32_t*)&h0, *(uint32_t*)&h1);
        }
    }
    __syncthreads();

    uint32_t b[4][8][2];
#pragma unroll
    for (int k16 = 0; k16 < 4; k16++) {
#pragma unroll
        for (int fj = 0; fj < 8; fj++) {
            int n  = fj * 8 + lg;
            int k0 = k16 * 16 + lc * 2;
            int k1 = k0 + 8;
            __nv_bfloat162 p0 = __floats2bfloat162_rn(Wf[k0 * PJ_WST + n], Wf[(k0 + 1) * PJ_WST + n]);
            __nv_bfloat162 p1 = __floats2bfloat162_rn(Wf[k1 * PJ_WST + n], Wf[(k1 + 1) * PJ_WST + n]);
            b[k16][fj][0] = *(uint32_t*)&p0;
            b[k16][fj][1] = *(uint32_t*)&p1;
        }
    }

    float d[8][4];
#pragma unroll
    for (int j = 0; j < 8; j++)
#pragma unroll
        for (int q = 0; q < 4; q++) d[j][q] = 0.0f;

    uint32_t xs_base = smem_u32(Xs);
    int r_a = lane & 15, ka = (lane >> 4) * 8;
    uint32_t a_addr0 = xs_base + (uint32_t)((wid * 16 + r_a) * PJ_XST + ka) * 2u;

#pragma unroll
    for (int k16 = 0; k16 < 4; k16++) {
        uint32_t a[4];
        LDMATRIX_X4(a[0], a[1], a[2], a[3], a_addr0 + (uint32_t)(k16 * 16 * 2));
#pragma unroll
        for (int fj = 0; fj < 8; fj++) mma_bf16(d[fj], a, b[k16][fj]);
    }
    __syncthreads();

#pragma unroll
    for (int fj = 0; fj < 8; fj++) {
        int n    = fj * 8 + lc * 2;
        int vlo  = wid * 16 + lg;
        int vhi  = vlo + 8;
        Ys[n * PJ_YST + vlo]       = __float2bfloat16_rn(d[fj][0]);
        Ys[(n + 1) * PJ_YST + vlo] = __float2bfloat16_rn(d[fj][1]);
        Ys[n * PJ_YST + vhi]       = __float2bfloat16_rn(d[fj][2]);
        Ys[(n + 1) * PJ_YST + vhi] = __float2bfloat16_rn(d[fj][3]);
    }
    __syncthreads();

#pragma unroll
    for (int s = tid; s < 1024; s += 256) {
        int n = s >> 4, vq = s & 15;
        uint4 val = *(uint4*)&Ys[n * PJ_YST + vq * 8];
        *(uint4*)&g_xT[(size_t)(ab * 64 + n) * V + v0 + vq * 8] = val;
    }
}

// ---------------------------------------------------------------------------
// agg: mma.sync bf16 GEMM, CTA 128x128, 8 warps (warp 64x32), OCCUPANCY 2
// KC=64, 3-stage cp.async pipeline, one __syncthreads per chunk
// ---------------------------------------------------------------------------
#define MT 128
#define NT 128
#define KC 64
#define NCHUNK (V / KC)               // 32
#define LDS_STRIDE 72                 // halves per row (144 B, ldmatrix bank-free)
#define A_HALVES (MT * LDS_STRIDE)    // 9216
#define B_HALVES (NT * LDS_STRIDE)    // 9216
#define ST_HALVES (A_HALVES + B_HALVES)
#define SM_BYTES (3 * ST_HALVES * 2)  // 110592 B -> 2 CTAs/SM = 216 KB

__device__ __forceinline__ void load_chunk(uint32_t smem_base, int stage,
                                           int j0, int n0, int k0, int tid) {
    uint32_t sa = smem_base + (uint32_t)stage * ((uint32_t)ST_HALVES * 2u);
    uint32_t sb = sa + (uint32_t)A_HALVES * 2u;
    // A: 128 rows x 128B = 1024 16B-segs (4/thread)
#pragma unroll
    for (int q = 0; q < 4; q++) {
        int s = tid + q * 256;
        int r = s >> 3, o = s & 7;
        uint32_t dst = sa + (uint32_t)(r * LDS_STRIDE + o * 8) * 2u;
        CP_ASYNC16(dst, &g_adjT[(size_t)(j0 + r) * V + k0 + o * 8]);
    }
    // B: 128 rows x 128B = 1024 16B-segs (4/thread)
#pragma unroll
    for (int q = 0; q < 4; q++) {
        int s = tid + q * 256;
        int r = s >> 3, o = s & 7;
        uint32_t dst = sb + (uint32_t)(r * LDS_STRIDE + o * 8) * 2u;
        CP_ASYNC16(dst, &g_xT[(size_t)(n0 + r) * V + k0 + o * 8]);
    }
}

__global__ void __launch_bounds__(256, 2) agg_mma_kernel(const float* __restrict__ bias,
                                                         float* __restrict__ out) {
    extern __shared__ __align__(16) __nv_bfloat16 smem[];
    uint32_t smem_base = smem_u32(smem);
    int tid  = threadIdx.x;
    int wid  = tid >> 5, lane = tid & 31;
    int j0   = blockIdx.x * MT;
    int n0   = blockIdx.y * NT;
    int m0w  = (wid & 1) * 64;        // warp m offset (2 warps over 128)
    int n0w  = (wid >> 1) * 32;       // warp n offset (4 warps over 128)
    int lg   = lane >> 2, lc = lane & 3;

    int r_a   = lane & 15;
    int ka    = (lane >> 4) * 8;
    int n_off = (lane & 7) + ((lane >> 4) & 1) * 8;
    int k_off = ((lane >> 3) & 1) * 8;

    float d[4][4][4];
#pragma unroll
    for (int i = 0; i < 4; i++)
#pragma unroll
        for (int j = 0; j < 4; j++)
#pragma unroll
            for (int q = 0; q < 4; q++) d[i][j][q] = 0.0f;

    load_chunk(smem_base, 0, j0, n0, 0, tid);   CP_COMMIT();
    load_chunk(smem_base, 1, j0, n0, KC, tid);  CP_COMMIT();

    for (int i = 0; i < NCHUNK; i++) {
        if (i < NCHUNK - 1) { CP_WAIT(1); } else { CP_WAIT(0); }
        __syncthreads();   // chunk i resident; releases stage (i-1)%3

        int stage = i % 3;
        uint32_t As = smem_base + (uint32_t)stage * ((uint32_t)ST_HALVES * 2u);
        uint32_t Bs = As + (uint32_t)A_HALVES * 2u;
        uint32_t a_base = As + (uint32_t)((m0w + r_a) * LDS_STRIDE + ka) * 2u;
        uint32_t b_base = Bs + (uint32_t)((n0w + n_off) * LDS_STRIDE + k_off) * 2u;

#pragma unroll
        for (int k16 = 0; k16 < 4; k16++) {
            uint32_t kb2 = (uint32_t)(k16 * 16 * 2);
            uint32_t a[4][4], b[4][2];
#pragma unroll
            for (int fi = 0; fi < 4; fi++) {
                LDMATRIX_X4(a[fi][0], a[fi][1], a[fi][2], a[fi][3],
                            a_base + (uint32_t)(fi * 16 * LDS_STRIDE * 2) + kb2);
            }
#pragma unroll
            for (int p = 0; p < 2; p++) {
                LDMATRIX_X4(b[2 * p][0], b[2 * p][1], b[2 * p + 1][0], b[2 * p + 1][1],
                            b_base + (uint32_t)(p * 16 * LDS_STRIDE * 2) + kb2);
            }
#pragma unroll
            for (int fi = 0; fi < 4; fi++)
#pragma unroll
                for (int fj = 0; fj < 4; fj++)
                    mma_bf16(d[fi][fj], a[fi], b[fj]);
        }
        // 3-stage ring: load (i+2) targets stage (i+2)%3, last computed in
        // iter i-1, protected by the barrier above — no second barrier.
        if (i + 2 < NCHUNK) {
            load_chunk(smem_base, (i + 2) % 3, j0, n0, (i + 2) * KC, tid);
            CP_COMMIT();
        }
    }

    // epilogue
#pragma unroll
    for (int fi = 0; fi < 4; fi++) {
        int row_lo = j0 + m0w + fi * 16 + lg;
        int row_hi = row_lo + 8;
        float rlo = g_rinv[row_lo];
        float rhi = g_rinv[row_hi];
#pragma unroll
        for (int fj = 0; fj < 4; fj++) {
            int c  = n0 + n0w + fj * 8 + lc * 2;
            int ab = c >> 6;
            int dd = c & 63;
            float2 bi = *(const float2*)&bias[dd];
            float2 olo, ohi;
            olo.x = fmaxf(bi.x + rlo * d[fi][fj][0], 0.0f);
            olo.y = fmaxf(bi.y + rlo * d[fi][fj][1], 0.0f);
            ohi.x = fmaxf(bi.x + rhi * d[fi][fj][2], 0.0f);
            ohi.y = fmaxf(bi.y + rhi * d[fi][fj][3], 0.0f);
            *(float2*)&out[((size_t)ab * V + row_lo) * DOUT + dd] = olo;
            *(float2*)&out[((size_t)ab * V + row_hi) * DOUT + dd] = ohi;
        }
    }
}

// ---------------------------------------------------------------------------
extern "C" void kernel_launch(void* const* d_in, const int* in_sizes, int n_in,
                              void* d_out, int out_size) {
    const float* adj  = (const float*)d_in[0];
    const float* x    = (const float*)d_in[1];
    const float* w    = (const float*)d_in[2];
    const float* bias = (const float*)d_in[3];
    float* out        = (float*)d_out;

    cudaFuncSetAttribute(agg_mma_kernel, cudaFuncAttributeMaxDynamicSharedMemorySize, SM_BYTES);

    colsum_partial_kernel<<<dim3(8, 32), 256>>>(adj);
    finalize_rinv_kernel<<<8, 256>>>();
    transpose_kernel<<<dim3(32, 32), 256>>>(adj);
    project_mma_kernel<<<dim3(V / 128, NB), 256>>>(x, w);
    agg_mma_kernel<<<dim3(V / MT, NCOL / NT), 256, SM_BYTES>>>(bias, out);
}

// round 12
// speedup vs baseline: 6.7411x; 1.0633x over previous
#include <cuda_runtime.h>
#include <cuda_bf16.h>
#include <cstdint>

#define V     2048
#define DIN   64
#define DOUT  64
#define NB    64            // A*B = 8*8
#define NCOL  (NB * DOUT)   // 4096 columns of the big GEMM

// ---------------- scratch (device globals; no cudaMalloc allowed) ----------
__device__ __nv_bfloat16 g_adjT[(size_t)V * V];   // 8 MB: adjT[j][v] = bf16(adj[v][j]*rinv[v])
__device__ __nv_bfloat16 g_xT[(size_t)NCOL * V];  // 16 MB: xT[c][v] = bf16((x@W)[ab,v,d])
__device__ float g_part[32][V];                   // colsum partials (overwritten fully each run)
__device__ float g_rinv[V];

// ---------------- helpers ---------------------------------------------------
__device__ __forceinline__ uint32_t smem_u32(const void* p) {
    uint32_t a;
    asm("{ .reg .u64 t; cvta.to.shared.u64 t, %1; cvt.u32.u64 %0, t; }" : "=r"(a) : "l"(p));
    return a;
}
#define CP_ASYNC16(dst, src) \
    asm volatile("cp.async.cg.shared.global [%0], [%1], 16;" :: "r"(dst), "l"(src) : "memory")
#define CP_COMMIT() asm volatile("cp.async.commit_group;" ::: "memory")
#define CP_WAIT(n)  asm volatile("cp.async.wait_group %0;" :: "n"(n) : "memory")

// m16n8k16 bf16 mma: D += A*B, fp32 accum
__device__ __forceinline__ void mma_bf16(float* d, const uint32_t* a, const uint32_t* b) {
    asm volatile(
        "mma.sync.aligned.m16n8k16.row.col.f32.bf16.bf16.f32 "
        "{%0,%1,%2,%3}, {%4,%5,%6,%7}, {%8,%9}, {%0,%1,%2,%3};"
        : "+f"(d[0]), "+f"(d[1]), "+f"(d[2]), "+f"(d[3])
        : "r"(a[0]), "r"(a[1]), "r"(a[2]), "r"(a[3]), "r"(b[0]), "r"(b[1]));
}
#define LDMATRIX_X4(r0, r1, r2, r3, addr) \
    asm volatile("ldmatrix.sync.aligned.m8n8.x4.shared.b16 {%0,%1,%2,%3}, [%4];" \
        : "=r"(r0), "=r"(r1), "=r"(r2), "=r"(r3) : "r"(addr))

// ---------------------------------------------------------------------------
// Fused launch 1: blocks [0,1024) = project, blocks [1024,1280) = colsum.
// Independent: colsum writes g_part; project writes g_xT.
//
// project: xT[(ab*64+d)][v] = bf16( sum_k x[ab,v,k] * W[k,d] ) via bf16 mma.
//   smem: Wth[d][k] bf16 transposed (b-frags = single uint32 LDS each),
//         Xs bf16 staged x (ldmatrix A-frags); Ys aliases Xs for transpose out.
// ---------------------------------------------------------------------------
#define PJ_WTST  72                  // Wth row stride (halves)
#define PJ_XST   72                  // Xs row stride (halves)
#define PJ_YST   136                 // Ys row stride (halves)
#define PJ_WT_BYTES (DOUT * PJ_WTST * 2)       // 9216
#define PJ_XS_BYTES (128 * PJ_XST * 2)         // 18432 (Ys needs 64*136*2=17408 <=)

__global__ void __launch_bounds__(256) fused_proj_colsum_kernel(
        const float* __restrict__ x, const float* __restrict__ w,
        const float* __restrict__ adj) {
    __shared__ __align__(16) char smem_raw[PJ_WT_BYTES + PJ_XS_BYTES];

    int tid = threadIdx.x;
    int b   = blockIdx.x;

    if (b >= 1024) {
        // ---- colsum partials: g_part[ib][j] = sum of 64 adj rows ----
        int cb = b - 1024;
        int j  = (cb & 7) * 256 + tid;
        int i0 = (cb >> 3) * 64;
        float s = 0.0f;
#pragma unroll 8
        for (int i = 0; i < 64; i++) s += adj[(size_t)(i0 + i) * V + j];
        g_part[cb >> 3][j] = s;
        return;
    }

    // ---- project ----
    __nv_bfloat16* Wth = (__nv_bfloat16*)smem_raw;                  // [d][k]
    __nv_bfloat16* Xs  = (__nv_bfloat16*)(smem_raw + PJ_WT_BYTES);  // [v][k]
    __nv_bfloat16* Ys  = Xs;                                        // reused

    int wid  = tid >> 5, lane = tid & 31;
    int lg   = lane >> 2, lc = lane & 3;
    int ab   = b >> 4;
    int v0   = (b & 15) * 128;

    // stage W transposed to bf16: Wth[d][k] = bf16(w[k][d])
#pragma unroll
    for (int s = tid; s < 1024; s += 256) {
        int k = s >> 4, dq = (s & 15) * 4;
        float4 f = *(const float4*)&w[k * DOUT + dq];
        Wth[(dq + 0) * PJ_WTST + k] = __float2bfloat16_rn(f.x);
        Wth[(dq + 1) * PJ_WTST + k] = __float2bfloat16_rn(f.y);
        Wth[(dq + 2) * PJ_WTST + k] = __float2bfloat16_rn(f.z);
        Wth[(dq + 3) * PJ_WTST + k] = __float2bfloat16_rn(f.w);
    }
    // stage x rows v0..v0+127 -> bf16 Xs
    {
        const float* xb = x + ((size_t)ab * V + v0) * DIN;
#pragma unroll
        for (int s = tid; s < 2048; s += 256) {
            int r = s >> 4, kq = s & 15;
            float4 f = *(const float4*)&xb[(size_t)r * DIN + kq * 4];
            __nv_bfloat162 h0 = __floats2bfloat162_rn(f.x, f.y);
            __nv_bfloat162 h1 = __floats2bfloat162_rn(f.z, f.w);
            *(uint2*)&Xs[r * PJ_XST + kq * 4] = make_uint2(*(uint32_t*)&h0, *(uint32_t*)&h1);
        }
    }
    __syncthreads();

    // b-frags: single uint32 LDS each — {W[k0][n], W[k0+1][n]} bf16 pair
    uint32_t bfr[4][8][2];
#pragma unroll
    for (int k16 = 0; k16 < 4; k16++) {
#pragma unroll
        for (int fj = 0; fj < 8; fj++) {
            int n  = fj * 8 + lg;
            int k0 = k16 * 16 + lc * 2;
            bfr[k16][fj][0] = *(const uint32_t*)&Wth[n * PJ_WTST + k0];
            bfr[k16][fj][1] = *(const uint32_t*)&Wth[n * PJ_WTST + k0 + 8];
        }
    }

    float d[8][4];
#pragma unroll
    for (int j = 0; j < 8; j++)
#pragma unroll
        for (int q = 0; q < 4; q++) d[j][q] = 0.0f;

    uint32_t xs_base = smem_u32(Xs);
    int r_a = lane & 15, ka = (lane >> 4) * 8;
    uint32_t a_addr0 = xs_base + (uint32_t)((wid * 16 + r_a) * PJ_XST + ka) * 2u;

#pragma unroll
    for (int k16 = 0; k16 < 4; k16++) {
        uint32_t a[4];
        LDMATRIX_X4(a[0], a[1], a[2], a[3], a_addr0 + (uint32_t)(k16 * 16 * 2));
#pragma unroll
        for (int fj = 0; fj < 8; fj++) mma_bf16(d[fj], a, bfr[k16][fj]);
    }
    __syncthreads();   // all Xs reads done; reuse as Ys

#pragma unroll
    for (int fj = 0; fj < 8; fj++) {
        int n    = fj * 8 + lc * 2;
        int vlo  = wid * 16 + lg;
        int vhi  = vlo + 8;
        Ys[n * PJ_YST + vlo]       = __float2bfloat16_rn(d[fj][0]);
        Ys[(n + 1) * PJ_YST + vlo] = __float2bfloat16_rn(d[fj][1]);
        Ys[n * PJ_YST + vhi]       = __float2bfloat16_rn(d[fj][2]);
        Ys[(n + 1) * PJ_YST + vhi] = __float2bfloat16_rn(d[fj][3]);
    }
    __syncthreads();

#pragma unroll
    for (int s = tid; s < 1024; s += 256) {
        int n = s >> 4, vq = s & 15;
        uint4 val = *(uint4*)&Ys[n * PJ_YST + vq * 8];
        *(uint4*)&g_xT[(size_t)(ab * 64 + n) * V + v0 + vq * 8] = val;
    }
}

// ---------------------------------------------------------------------------
// transpose (+inline rinv): adjT[j][v] = bf16(adj[v][j] * rinv[v])
//   rinv computed per block from g_part (same order as old finalize — bitwise
//   identical); blocks with blockIdx.x==0 publish g_rinv for agg epilogue.
// ---------------------------------------------------------------------------
__global__ void __launch_bounds__(256) transpose_kernel(const float* __restrict__ adj) {
    __shared__ float ts[64][65];   // ts[j][v]
    __shared__ float rs[64];
    int tid = threadIdx.x;
    int j0 = blockIdx.x * 64, v0 = blockIdx.y * 64;

#pragma unroll
    for (int p = 0; p < 4; p++) {
        int r = p * 16 + (tid >> 4);
        int c = (tid & 15) * 4;
        float4 f = *(const float4*)&adj[(size_t)(v0 + r) * V + j0 + c];
        ts[c + 0][r] = f.x;
        ts[c + 1][r] = f.y;
        ts[c + 2][r] = f.z;
        ts[c + 3][r] = f.w;
    }
    if (tid < 64) {
        float s = 0.0f;
#pragma unroll
        for (int i = 0; i < 32; i++) s += g_part[i][v0 + tid];
        float r = rsqrtf(s);
        rs[tid] = r;
        if (blockIdx.x == 0) g_rinv[v0 + tid] = r;
    }
    __syncthreads();

#pragma unroll
    for (int p = 0; p < 2; p++) {
        int jr = p * 32 + (tid >> 3);
        int vo = (tid & 7) * 8;
        __nv_bfloat16 h[8];
#pragma unroll
        for (int i = 0; i < 8; i++)
            h[i] = __float2bfloat16_rn(ts[jr][vo + i] * rs[vo + i]);
        *(uint4*)&g_adjT[(size_t)(j0 + jr) * V + v0 + vo] = *(uint4*)h;
    }
}

// ---------------------------------------------------------------------------
// agg: mma.sync bf16 GEMM, CTA 128x128, 8 warps (warp 64x32), OCCUPANCY 2
// KC=64, 3-stage cp.async pipeline, one __syncthreads per chunk
// ---------------------------------------------------------------------------
#define MT 128
#define NT 128
#define KC 64
#define NCHUNK (V / KC)               // 32
#define LDS_STRIDE 72                 // halves per row (144 B, ldmatrix bank-free)
#define A_HALVES (MT * LDS_STRIDE)    // 9216
#define B_HALVES (NT * LDS_STRIDE)    // 9216
#define ST_HALVES (A_HALVES + B_HALVES)
#define SM_BYTES (3 * ST_HALVES * 2)  // 110592 B -> 2 CTAs/SM = 216 KB

__device__ __forceinline__ void load_chunk(uint32_t smem_base, int stage,
                                           int j0, int n0, int k0, int tid) {
    uint32_t sa = smem_base + (uint32_t)stage * ((uint32_t)ST_HALVES * 2u);
    uint32_t sb = sa + (uint32_t)A_HALVES * 2u;
#pragma unroll
    for (int q = 0; q < 4; q++) {
        int s = tid + q * 256;
        int r = s >> 3, o = s & 7;
        uint32_t dst = sa + (uint32_t)(r * LDS_STRIDE + o * 8) * 2u;
        CP_ASYNC16(dst, &g_adjT[(size_t)(j0 + r) * V + k0 + o * 8]);
    }
#pragma unroll
    for (int q = 0; q < 4; q++) {
        int s = tid + q * 256;
        int r = s >> 3, o = s & 7;
        uint32_t dst = sb + (uint32_t)(r * LDS_STRIDE + o * 8) * 2u;
        CP_ASYNC16(dst, &g_xT[(size_t)(n0 + r) * V + k0 + o * 8]);
    }
}

__global__ void __launch_bounds__(256, 2) agg_mma_kernel(const float* __restrict__ bias,
                                                         float* __restrict__ out) {
    extern __shared__ __align__(16) __nv_bfloat16 smem[];
    uint32_t smem_base = smem_u32(smem);
    int tid  = threadIdx.x;
    int wid  = tid >> 5, lane = tid & 31;
    int j0   = blockIdx.x * MT;
    int n0   = blockIdx.y * NT;
    int m0w  = (wid & 1) * 64;
    int n0w  = (wid >> 1) * 32;
    int lg   = lane >> 2, lc = lane & 3;

    int r_a   = lane & 15;
    int ka    = (lane >> 4) * 8;
    int n_off = (lane & 7) + ((lane >> 4) & 1) * 8;
    int k_off = ((lane >> 3) & 1) * 8;

    float d[4][4][4];
#pragma unroll
    for (int i = 0; i < 4; i++)
#pragma unroll
        for (int j = 0; j < 4; j++)
#pragma unroll
            for (int q = 0; q < 4; q++) d[i][j][q] = 0.0f;

    load_chunk(smem_base, 0, j0, n0, 0, tid);   CP_COMMIT();
    load_chunk(smem_base, 1, j0, n0, KC, tid);  CP_COMMIT();

    for (int i = 0; i < NCHUNK; i++) {
        if (i < NCHUNK - 1) { CP_WAIT(1); } else { CP_WAIT(0); }
        __syncthreads();   // chunk i resident; releases stage (i-1)%3

        int stage = i % 3;
        uint32_t As = smem_base + (uint32_t)stage * ((uint32_t)ST_HALVES * 2u);
        uint32_t Bs = As + (uint32_t)A_HALVES * 2u;
        uint32_t a_base = As + (uint32_t)((m0w + r_a) * LDS_STRIDE + ka) * 2u;
        uint32_t b_base = Bs + (uint32_t)((n0w + n_off) * LDS_STRIDE + k_off) * 2u;

#pragma unroll
        for (int k16 = 0; k16 < 4; k16++) {
            uint32_t kb2 = (uint32_t)(k16 * 16 * 2);
            uint32_t a[4][4], b[4][2];
#pragma unroll
            for (int fi = 0; fi < 4; fi++) {
                LDMATRIX_X4(a[fi][0], a[fi][1], a[fi][2], a[fi][3],
                            a_base + (uint32_t)(fi * 16 * LDS_STRIDE * 2) + kb2);
            }
#pragma unroll
            for (int p = 0; p < 2; p++) {
                LDMATRIX_X4(b[2 * p][0], b[2 * p][1], b[2 * p + 1][0], b[2 * p + 1][1],
                            b_base + (uint32_t)(p * 16 * LDS_STRIDE * 2) + kb2);
            }
#pragma unroll
            for (int fi = 0; fi < 4; fi++)
#pragma unroll
                for (int fj = 0; fj < 4; fj++)
                    mma_bf16(d[fi][fj], a[fi], b[fj]);
        }
        if (i + 2 < NCHUNK) {
            load_chunk(smem_base, (i + 2) % 3, j0, n0, (i + 2) * KC, tid);
            CP_COMMIT();
        }
    }

    // epilogue
#pragma unroll
    for (int fi = 0; fi < 4; fi++) {
        int row_lo = j0 + m0w + fi * 16 + lg;
        int row_hi = row_lo + 8;
        float rlo = g_rinv[row_lo];
        float rhi = g_rinv[row_hi];
#pragma unroll
        for (int fj = 0; fj < 4; fj++) {
            int c  = n0 + n0w + fj * 8 + lc * 2;
            int ab = c >> 6;
            int dd = c & 63;
            float2 bi = *(const float2*)&bias[dd];
            float2 olo, ohi;
            olo.x = fmaxf(bi.x + rlo * d[fi][fj][0], 0.0f);
            olo.y = fmaxf(bi.y + rlo * d[fi][fj][1], 0.0f);
            ohi.x = fmaxf(bi.x + rhi * d[fi][fj][2], 0.0f);
            ohi.y = fmaxf(bi.y + rhi * d[fi][fj][3], 0.0f);
            *(float2*)&out[((size_t)ab * V + row_lo) * DOUT + dd] = olo;
            *(float2*)&out[((size_t)ab * V + row_hi) * DOUT + dd] = ohi;
        }
    }
}

// ---------------------------------------------------------------------------
extern "C" void kernel_launch(void* const* d_in, const int* in_sizes, int n_in,
                              void* d_out, int out_size) {
    const float* adj  = (const float*)d_in[0];
    const float* x    = (const float*)d_in[1];
    const float* w    = (const float*)d_in[2];
    const float* bias = (const float*)d_in[3];
    float* out        = (float*)d_out;

    cudaFuncSetAttribute(agg_mma_kernel, cudaFuncAttributeMaxDynamicSharedMemorySize, SM_BYTES);

    fused_proj_colsum_kernel<<<1280, 256>>>(x, w, adj);
    transpose_kernel<<<dim3(32, 32), 256>>>(adj);
    agg_mma_kernel<<<dim3(V / MT, NCOL / NT), 256, SM_BYTES>>>(bias, out);
}